// round 3
// baseline (speedup 1.0000x reference)
#include <cuda_runtime.h>
#include <cuda_bf16.h>
#include <math.h>

// ---------------------------------------------------------------------------
// HydraBlock: B=4 T=2048 D=1024 H=16 HD=64 L=64 E=8   (8192 tokens)
// fp32 SIMT baseline. All scratch in __device__ globals (no allocations).
// ---------------------------------------------------------------------------

#define MTOK   8192
#define DMODEL 1024
#define NHEAD  16
#define HDIM   64
#define DLAT   64
#define NEXP   8
#define EPS    1e-6f

__device__ __align__(16) float g_h[MTOK * DMODEL];       // rmsnorm1(x)
__device__ __align__(16) float g_q[MTOK * DMODEL];       // query
__device__ __align__(16) float g_dl[MTOK * DLAT];        // latent
__device__ __align__(16) float g_kv[MTOK * 2 * DMODEL];  // kv up-projection
__device__ __align__(16) float g_att[MTOK * DMODEL];     // attention output
__device__ __align__(16) float g_x1[MTOK * DMODEL];      // x + attn branch
__device__ __align__(16) float g_h2[MTOK * DMODEL];      // rmsnorm2(x1)
__device__ __align__(16) float g_gate[MTOK * NEXP];      // softmax gate

// ---------------------------------------------------------------------------
// rmsnorm: one block per token, 256 threads, float4 per thread
// ---------------------------------------------------------------------------
__global__ void rmsnorm_kernel(const float* __restrict__ x,
                               const float* __restrict__ gamma,
                               float* __restrict__ h) {
    int t = blockIdx.x;
    int tid = threadIdx.x;
    const float4* xr = (const float4*)(x + (size_t)t * DMODEL);
    float4 v = xr[tid];
    float ss = v.x * v.x + v.y * v.y + v.z * v.z + v.w * v.w;
    #pragma unroll
    for (int o = 16; o; o >>= 1) ss += __shfl_xor_sync(0xffffffffu, ss, o);
    __shared__ float sred[8];
    if ((tid & 31) == 0) sred[tid >> 5] = ss;
    __syncthreads();
    if (tid < 8) {
        float s = sred[tid];
        #pragma unroll
        for (int o = 4; o; o >>= 1) s += __shfl_xor_sync(0xffu, s, o);
        if (tid == 0) sred[0] = s;
    }
    __syncthreads();
    float inv = rsqrtf(sred[0] * (1.0f / DMODEL) + EPS);
    float4 g = ((const float4*)gamma)[tid];
    float4 o;
    o.x = g.x * v.x * inv; o.y = g.y * v.y * inv;
    o.z = g.z * v.z * inv; o.w = g.w * v.w * inv;
    ((float4*)(h + (size_t)t * DMODEL))[tid] = o;
}

// ---------------------------------------------------------------------------
// Tiled SGEMM: C = A[M,K] @ B[K,N] + bias[N] (+ optional residual R[M,N])
// Exact-tiling only (all dims divide the tile sizes used below).
// ---------------------------------------------------------------------------
template <int BM, int BN, int BK, int TM, int TN>
__global__ void __launch_bounds__((BM / TM) * (BN / TN))
sgemm_bias(const float* __restrict__ A,
           const float* __restrict__ Bm,
           const float* __restrict__ bias,
           const float* __restrict__ Res,
           float* __restrict__ C,
           int M, int N, int K) {
    constexpr int THREADS = (BM / TM) * (BN / TN);
    __shared__ float As[BK][BM];
    __shared__ float Bs[BK][BN];
    int bx = blockIdx.x, by = blockIdx.y;
    int tid = threadIdx.x;
    int tx = tid % (BN / TN);
    int ty = tid / (BN / TN);

    const float* Ablk = A + (size_t)by * BM * K;
    const float* Bblk = Bm + (size_t)bx * BN;

    float acc[TM][TN];
    #pragma unroll
    for (int i = 0; i < TM; i++)
        #pragma unroll
        for (int j = 0; j < TN; j++) acc[i][j] = 0.0f;

    constexpr int A_ITERS = BM * BK / (THREADS * 4);
    constexpr int B_ITERS = BK * BN / (THREADS * 4);

    for (int k0 = 0; k0 < K; k0 += BK) {
        #pragma unroll
        for (int it = 0; it < A_ITERS; ++it) {
            int idx = (tid + it * THREADS) * 4;
            int row = idx / BK, col = idx % BK;
            float4 v = *(const float4*)(Ablk + (size_t)row * K + k0 + col);
            As[col + 0][row] = v.x; As[col + 1][row] = v.y;
            As[col + 2][row] = v.z; As[col + 3][row] = v.w;
        }
        #pragma unroll
        for (int it = 0; it < B_ITERS; ++it) {
            int idx = (tid + it * THREADS) * 4;
            int row = idx / BN, col = idx % BN;
            *(float4*)(&Bs[row][col]) =
                *(const float4*)(Bblk + (size_t)(k0 + row) * N + col);
        }
        __syncthreads();
        #pragma unroll
        for (int k = 0; k < BK; k++) {
            float ar[TM], br[TN];
            #pragma unroll
            for (int i = 0; i < TM; i += 4)
                *(float4*)&ar[i] = *(float4*)&As[k][ty * TM + i];
            #pragma unroll
            for (int j = 0; j < TN; j += 4)
                *(float4*)&br[j] = *(float4*)&Bs[k][tx * TN + j];
            #pragma unroll
            for (int i = 0; i < TM; i++)
                #pragma unroll
                for (int j = 0; j < TN; j++)
                    acc[i][j] = fmaf(ar[i], br[j], acc[i][j]);
        }
        __syncthreads();
    }

    #pragma unroll
    for (int i = 0; i < TM; i++) {
        int row = by * BM + ty * TM + i;
        #pragma unroll
        for (int j = 0; j < TN; j += 4) {
            int col = bx * BN + tx * TN + j;
            float4 bsv = *(const float4*)(bias + col);
            float4 r;
            r.x = acc[i][j + 0] + bsv.x;
            r.y = acc[i][j + 1] + bsv.y;
            r.z = acc[i][j + 2] + bsv.z;
            r.w = acc[i][j + 3] + bsv.w;
            if (Res) {
                float4 rr = *(const float4*)(Res + (size_t)row * N + col);
                r.x += rr.x; r.y += rr.y; r.z += rr.z; r.w += rr.w;
            }
            *(float4*)(C + (size_t)row * N + col) = r;
        }
    }
}

// ---------------------------------------------------------------------------
// Per-token head-mixing attention. One block (256 thr) per token.
// q[t]: [16,64]; kv[t]: [16,128] (first 64 = k, last 64 = v)
// ---------------------------------------------------------------------------
__global__ void attn_kernel(const float* __restrict__ q,
                            const float* __restrict__ kv,
                            float* __restrict__ out) {
    int t = blockIdx.x;
    int tid = threadIdx.x;
    __shared__ float sq[DMODEL];
    __shared__ float skv[2 * DMODEL];
    __shared__ float sp[NHEAD * NHEAD];

    ((float4*)sq)[tid] = ((const float4*)(q + (size_t)t * DMODEL))[tid];
    ((float4*)skv)[tid]       = ((const float4*)(kv + (size_t)t * 2 * DMODEL))[tid];
    ((float4*)skv)[tid + 256] = ((const float4*)(kv + (size_t)t * 2 * DMODEL))[tid + 256];
    __syncthreads();

    // scores: one (h,g) pair per thread
    {
        int h = tid >> 4, g = tid & 15;
        const float* qh = sq + h * HDIM;
        const float* kg = skv + g * 2 * HDIM;
        float s = 0.0f;
        #pragma unroll
        for (int d = 0; d < HDIM; d++) s = fmaf(qh[d], kg[d], s);
        sp[tid] = s * 0.125f;  // 1/sqrt(64)
    }
    __syncthreads();

    if (tid < NHEAD) {  // softmax over g for row h=tid
        float mx = -1e30f;
        #pragma unroll
        for (int g = 0; g < NHEAD; g++) mx = fmaxf(mx, sp[tid * NHEAD + g]);
        float sum = 0.0f;
        #pragma unroll
        for (int g = 0; g < NHEAD; g++) {
            float e = expf(sp[tid * NHEAD + g] - mx);
            sp[tid * NHEAD + g] = e;
            sum += e;
        }
        float invs = 1.0f / sum;
        #pragma unroll
        for (int g = 0; g < NHEAD; g++) sp[tid * NHEAD + g] *= invs;
    }
    __syncthreads();

    // out[h,dd] = sum_g p[h,g] * v[g,dd]; 1024 outputs / 256 threads
    #pragma unroll
    for (int r = 0; r < 4; r++) {
        int o = tid + r * 256;
        int h = o >> 6, dd = o & 63;
        float acc = 0.0f;
        #pragma unroll
        for (int g = 0; g < NHEAD; g++)
            acc = fmaf(sp[h * NHEAD + g], skv[g * 2 * HDIM + HDIM + dd], acc);
        out[(size_t)t * DMODEL + o] = acc;
    }
}

// ---------------------------------------------------------------------------
// Fused rmsnorm2 + gate softmax. One block (256 thr) per token.
// ---------------------------------------------------------------------------
__global__ void rms2_gate_kernel(const float* __restrict__ x1,
                                 const float* __restrict__ gamma,
                                 const float* __restrict__ Wg,
                                 const float* __restrict__ bg,
                                 float* __restrict__ h2,
                                 float* __restrict__ gate) {
    int t = blockIdx.x;
    int tid = threadIdx.x;
    float4 v = ((const float4*)(x1 + (size_t)t * DMODEL))[tid];
    float ss = v.x * v.x + v.y * v.y + v.z * v.z + v.w * v.w;
    #pragma unroll
    for (int o = 16; o; o >>= 1) ss += __shfl_xor_sync(0xffffffffu, ss, o);
    __shared__ float sred[8];
    __shared__ float swred[8][NEXP];
    __shared__ float slog[NEXP];
    if ((tid & 31) == 0) sred[tid >> 5] = ss;
    __syncthreads();
    if (tid < 8) {
        float s = sred[tid];
        #pragma unroll
        for (int o = 4; o; o >>= 1) s += __shfl_xor_sync(0xffu, s, o);
        if (tid == 0) sred[0] = s;
    }
    __syncthreads();
    float inv = rsqrtf(sred[0] * (1.0f / DMODEL) + EPS);
    float4 g = ((const float4*)gamma)[tid];
    float4 hv;
    hv.x = g.x * v.x * inv; hv.y = g.y * v.y * inv;
    hv.z = g.z * v.z * inv; hv.w = g.w * v.w * inv;
    ((float4*)(h2 + (size_t)t * DMODEL))[tid] = hv;

    // gate logits: thread owns d0..d0+3; Wg is [D, E] row-major
    int d0 = tid * 4;
    float pe[NEXP];
    #pragma unroll
    for (int e = 0; e < NEXP; e++) {
        pe[e] = hv.x * Wg[(d0 + 0) * NEXP + e]
              + hv.y * Wg[(d0 + 1) * NEXP + e]
              + hv.z * Wg[(d0 + 2) * NEXP + e]
              + hv.w * Wg[(d0 + 3) * NEXP + e];
    }
    #pragma unroll
    for (int e = 0; e < NEXP; e++)
        #pragma unroll
        for (int o = 16; o; o >>= 1)
            pe[e] += __shfl_xor_sync(0xffffffffu, pe[e], o);
    if ((tid & 31) == 0)
        #pragma unroll
        for (int e = 0; e < NEXP; e++) swred[tid >> 5][e] = pe[e];
    __syncthreads();
    if (tid < NEXP) {
        float lg = bg[tid];
        #pragma unroll
        for (int w = 0; w < 8; w++) lg += swred[w][tid];
        slog[tid] = lg;
    }
    __syncthreads();
    if (tid < NEXP) {
        float mx = slog[0];
        #pragma unroll
        for (int e = 1; e < NEXP; e++) mx = fmaxf(mx, slog[e]);
        float sum = 0.0f;
        #pragma unroll
        for (int e = 0; e < NEXP; e++) sum += expf(slog[e] - mx);
        gate[(size_t)t * NEXP + tid] = expf(slog[tid] - mx) / sum;
    }
}

// ---------------------------------------------------------------------------
// MoE GEMM: out[m,f] = Res[m,f] + sum_k Ahat[m,k] * We_flat[k,f]
//   k = e*1024 + d ; Ahat[m,k] = gate[m,e] * h2[m,d]
//   We [E,D,D] row-major == We_flat [8192, 1024] row-major.
// A tile built on the fly (e is constant within an 8-wide, aligned K-tile).
// ---------------------------------------------------------------------------
template <int BM, int BN, int BK, int TM, int TN>
__global__ void __launch_bounds__((BM / TM) * (BN / TN))
moe_gemm(const float* __restrict__ h2,
         const float* __restrict__ gate,
         const float* __restrict__ We,
         const float* __restrict__ Res,
         float* __restrict__ C,
         int M, int N, int K) {
    constexpr int THREADS = (BM / TM) * (BN / TN);
    __shared__ float As[BK][BM];
    __shared__ float Bs[BK][BN];
    int bx = blockIdx.x, by = blockIdx.y;
    int tid = threadIdx.x;
    int tx = tid % (BN / TN);
    int ty = tid / (BN / TN);

    const float* Bblk = We + (size_t)bx * BN;

    float acc[TM][TN];
    #pragma unroll
    for (int i = 0; i < TM; i++)
        #pragma unroll
        for (int j = 0; j < TN; j++) acc[i][j] = 0.0f;

    constexpr int A_ITERS = BM * BK / (THREADS * 4);
    constexpr int B_ITERS = BK * BN / (THREADS * 4);

    for (int k0 = 0; k0 < K; k0 += BK) {
        int e = k0 >> 10;         // expert id, constant across the K-tile
        int dbase = k0 & 1023;    // offset within h2 row
        #pragma unroll
        for (int it = 0; it < A_ITERS; ++it) {
            int idx = (tid + it * THREADS) * 4;
            int row = idx / BK, col = idx % BK;
            int grow = by * BM + row;
            float gt = __ldg(gate + (size_t)grow * NEXP + e);
            float4 v = *(const float4*)(h2 + (size_t)grow * DMODEL + dbase + col);
            As[col + 0][row] = v.x * gt; As[col + 1][row] = v.y * gt;
            As[col + 2][row] = v.z * gt; As[col + 3][row] = v.w * gt;
        }
        #pragma unroll
        for (int it = 0; it < B_ITERS; ++it) {
            int idx = (tid + it * THREADS) * 4;
            int row = idx / BN, col = idx % BN;
            *(float4*)(&Bs[row][col]) =
                *(const float4*)(Bblk + (size_t)(k0 + row) * N + col);
        }
        __syncthreads();
        #pragma unroll
        for (int k = 0; k < BK; k++) {
            float ar[TM], br[TN];
            #pragma unroll
            for (int i = 0; i < TM; i += 4)
                *(float4*)&ar[i] = *(float4*)&As[k][ty * TM + i];
            #pragma unroll
            for (int j = 0; j < TN; j += 4)
                *(float4*)&br[j] = *(float4*)&Bs[k][tx * TN + j];
            #pragma unroll
            for (int i = 0; i < TM; i++)
                #pragma unroll
                for (int j = 0; j < TN; j++)
                    acc[i][j] = fmaf(ar[i], br[j], acc[i][j]);
        }
        __syncthreads();
    }

    #pragma unroll
    for (int i = 0; i < TM; i++) {
        int row = by * BM + ty * TM + i;
        #pragma unroll
        for (int j = 0; j < TN; j += 4) {
            int col = bx * BN + tx * TN + j;
            float4 rr = *(const float4*)(Res + (size_t)row * N + col);
            float4 r;
            r.x = acc[i][j + 0] + rr.x;
            r.y = acc[i][j + 1] + rr.y;
            r.z = acc[i][j + 2] + rr.z;
            r.w = acc[i][j + 3] + rr.w;
            *(float4*)(C + (size_t)row * N + col) = r;
        }
    }
}

// ---------------------------------------------------------------------------
// launch
// ---------------------------------------------------------------------------
extern "C" void kernel_launch(void* const* d_in, const int* in_sizes, int n_in,
                              void* d_out, int out_size) {
    const float* x      = (const float*)d_in[0];
    const float* gamma1 = (const float*)d_in[1];
    const float* Wq     = (const float*)d_in[2];
    const float* bq     = (const float*)d_in[3];
    const float* Wdown  = (const float*)d_in[4];
    const float* bdown  = (const float*)d_in[5];
    const float* Wup    = (const float*)d_in[6];
    const float* bup    = (const float*)d_in[7];
    const float* Wo     = (const float*)d_in[8];
    const float* bo     = (const float*)d_in[9];
    const float* gamma2 = (const float*)d_in[10];
    const float* Wg     = (const float*)d_in[11];
    const float* bg     = (const float*)d_in[12];
    const float* We     = (const float*)d_in[13];
    float* out = (float*)d_out;

    float *h, *q, *dl, *kv, *att, *x1, *h2, *gate;
    cudaGetSymbolAddress((void**)&h,    g_h);
    cudaGetSymbolAddress((void**)&q,    g_q);
    cudaGetSymbolAddress((void**)&dl,   g_dl);
    cudaGetSymbolAddress((void**)&kv,   g_kv);
    cudaGetSymbolAddress((void**)&att,  g_att);
    cudaGetSymbolAddress((void**)&x1,   g_x1);
    cudaGetSymbolAddress((void**)&h2,   g_h2);
    cudaGetSymbolAddress((void**)&gate, g_gate);

    // 1. h = rmsnorm(x, gamma1)
    rmsnorm_kernel<<<MTOK, 256>>>(x, gamma1, h);

    // 2. q = h @ Wq + bq           [8192,1024] x [1024,1024]
    {
        dim3 grid(DMODEL / 128, MTOK / 128);
        sgemm_bias<128, 128, 8, 8, 8><<<grid, 256>>>(h, Wq, bq, nullptr, q,
                                                     MTOK, DMODEL, DMODEL);
    }
    // 3. dl = h @ Wdown + bdown    [8192,1024] x [1024,64]
    {
        dim3 grid(DLAT / 64, MTOK / 64);
        sgemm_bias<64, 64, 16, 4, 4><<<grid, 256>>>(h, Wdown, bdown, nullptr, dl,
                                                    MTOK, DLAT, DMODEL);
    }
    // 4. kv = dl @ Wup + bup       [8192,64] x [64,2048]
    {
        dim3 grid(2 * DMODEL / 128, MTOK / 128);
        sgemm_bias<128, 128, 8, 8, 8><<<grid, 256>>>(dl, Wup, bup, nullptr, kv,
                                                     MTOK, 2 * DMODEL, DLAT);
    }
    // 5. per-token head-mixing attention
    attn_kernel<<<MTOK, 256>>>(q, kv, att);

    // 6. x1 = x + att @ Wo + bo
    {
        dim3 grid(DMODEL / 128, MTOK / 128);
        sgemm_bias<128, 128, 8, 8, 8><<<grid, 256>>>(att, Wo, bo, x, x1,
                                                     MTOK, DMODEL, DMODEL);
    }
    // 7. h2 = rmsnorm(x1, gamma2); gate = softmax(h2 @ Wg + bg)
    rms2_gate_kernel<<<MTOK, 256>>>(x1, gamma2, Wg, bg, h2, gate);

    // 8. out = x1 + sum_e gate_e * (h2 @ We[e])   as one K=8192 GEMM
    {
        dim3 grid(DMODEL / 128, MTOK / 128);
        moe_gemm<128, 128, 8, 8, 8><<<grid, 256>>>(h2, gate, We, x1, out,
                                                   MTOK, DMODEL, NEXP * DMODEL);
    }
}

// round 5
// speedup vs baseline: 1.9385x; 1.9385x over previous
#include <cuda_runtime.h>
#include <cuda_bf16.h>
#include <math.h>
#include <stdint.h>

// ---------------------------------------------------------------------------
// HydraBlock: B=4 T=2048 D=1024 H=16 HD=64 L=64 E=8   (8192 tokens)
// TF32 tensor-core GEMMs for Wq / Wo / MoE; fp32 SIMT for the small stages.
// ---------------------------------------------------------------------------

#define MTOK   8192
#define DMODEL 1024
#define NHEAD  16
#define HDIM   64
#define DLAT   64
#define NEXP   8
#define EPS    1e-6f

__device__ __align__(16) float g_h[MTOK * DMODEL];       // rmsnorm1(x)
__device__ __align__(16) float g_q[MTOK * DMODEL];       // query
__device__ __align__(16) float g_dl[MTOK * DLAT];        // latent
__device__ __align__(16) float g_kv[MTOK * 2 * DMODEL];  // kv up-projection
__device__ __align__(16) float g_att[MTOK * DMODEL];     // attention output
__device__ __align__(16) float g_x1[MTOK * DMODEL];      // x + attn branch
__device__ __align__(16) float g_h2[MTOK * DMODEL];      // rmsnorm2(x1)
__device__ __align__(16) float g_gate[MTOK * NEXP];      // softmax gate

// ---------------------------------------------------------------------------
// tf32 helpers
// ---------------------------------------------------------------------------
__device__ __forceinline__ uint32_t f2tf(float x) {
    uint32_t r;
    asm("cvt.rna.tf32.f32 %0, %1;" : "=r"(r) : "f"(x));
    return r;
}
__device__ __forceinline__ float f2tff(float x) { return __uint_as_float(f2tf(x)); }

__device__ __forceinline__ void mma8(float c[4], const uint32_t a[4], const uint32_t b[2]) {
    asm volatile(
        "mma.sync.aligned.m16n8k8.row.col.f32.tf32.tf32.f32 "
        "{%0,%1,%2,%3}, {%4,%5,%6,%7}, {%8,%9}, {%0,%1,%2,%3};"
        : "+f"(c[0]), "+f"(c[1]), "+f"(c[2]), "+f"(c[3])
        : "r"(a[0]), "r"(a[1]), "r"(a[2]), "r"(a[3]), "r"(b[0]), "r"(b[1]));
}

// ---------------------------------------------------------------------------
// TF32 GEMM: C[M,N] = op(A)[M,K] @ B[K,N] (+bias) (+Res)
// MOE=1: A is h2 [M,1024] with K=8192 virtual; Ahat[m, e*1024+d] = gate[m,e]*h2[m,d]
// CTA tile 128x128x16, 8 warps (2x4), warp tile 64x32, m16n8k8 tf32 mma.
// ---------------------------------------------------------------------------
template <int MOE>
__global__ void __launch_bounds__(256, 1)
tf32_gemm(const float* __restrict__ A, const float* __restrict__ gate,
          const float* __restrict__ Bm, const float* __restrict__ bias,
          const float* __restrict__ Res, float* __restrict__ C,
          int M, int N, int K) {
    __shared__ float As[16][128 + 8];   // [k][m], stride 136 -> conflict-free frags
    __shared__ float Bs[16][128 + 8];   // [k][n]

    const int tid  = threadIdx.x;
    const int lane = tid & 31;
    const int wid  = tid >> 5;
    const int wm   = wid & 1;          // 0..1 : 64-row slice
    const int wn   = wid >> 1;         // 0..3 : 32-col slice
    const int bx   = blockIdx.x, by = blockIdx.y;

    const int astr = MOE ? DMODEL : K;  // A row stride

    float acc[4][4][4];
    #pragma unroll
    for (int i = 0; i < 4; i++)
        #pragma unroll
        for (int j = 0; j < 4; j++)
            #pragma unroll
            for (int r = 0; r < 4; r++) acc[i][j][r] = 0.0f;

    // global-load thread mapping
    const int arow = tid >> 2;          // 0..63 (+64 on iter 1)
    const int akc  = (tid & 3) << 2;    // 0,4,8,12
    const int bkr  = tid >> 5;          // 0..7  (+8 on iter 1)
    const int bnc  = (tid & 31) << 2;   // 0..124

    const float* Arow0 = A + (size_t)(by * 128 + arow) * astr;
    const float* Brow  = Bm + (size_t)bkr * N + bx * 128 + bnc;
    const float* Gp0   = MOE ? (gate + (size_t)(by * 128 + arow) * NEXP) : nullptr;

    float4 pa0, pa1, pb0, pb1;
    float g0 = 1.0f, g1 = 1.0f;

    auto prefetch = [&](int k0) {
        int ac = MOE ? (k0 & (DMODEL - 1)) : k0;
        const float* p0 = Arow0 + ac + akc;
        pa0 = *(const float4*)p0;
        pa1 = *(const float4*)(p0 + (size_t)64 * astr);
        const float* pb = Brow + (size_t)k0 * N;
        pb0 = *(const float4*)pb;
        pb1 = *(const float4*)(pb + (size_t)8 * N);
        if (MOE) {
            int e = k0 >> 10;
            g0 = __ldg(Gp0 + e);
            g1 = __ldg(Gp0 + (size_t)64 * NEXP + e);
        }
    };

    auto stage = [&]() {
        As[akc + 0][arow] = f2tff(pa0.x * g0);
        As[akc + 1][arow] = f2tff(pa0.y * g0);
        As[akc + 2][arow] = f2tff(pa0.z * g0);
        As[akc + 3][arow] = f2tff(pa0.w * g0);
        As[akc + 0][arow + 64] = f2tff(pa1.x * g1);
        As[akc + 1][arow + 64] = f2tff(pa1.y * g1);
        As[akc + 2][arow + 64] = f2tff(pa1.z * g1);
        As[akc + 3][arow + 64] = f2tff(pa1.w * g1);
        float4 t0, t1;
        t0.x = f2tff(pb0.x); t0.y = f2tff(pb0.y); t0.z = f2tff(pb0.z); t0.w = f2tff(pb0.w);
        t1.x = f2tff(pb1.x); t1.y = f2tff(pb1.y); t1.z = f2tff(pb1.z); t1.w = f2tff(pb1.w);
        *(float4*)&Bs[bkr][bnc]     = t0;
        *(float4*)&Bs[bkr + 8][bnc] = t1;
    };

    const int NT = K / 16;
    prefetch(0);
    for (int kt = 0; kt < NT; kt++) {
        stage();
        __syncthreads();
        if (kt + 1 < NT) prefetch((kt + 1) * 16);  // overlap next loads with mma

        #pragma unroll
        for (int ks = 0; ks < 2; ks++) {
            const int kb = ks * 8;
            const int kq = kb + (lane & 3);
            const int r0 = wm * 64 + (lane >> 2);
            const int c0 = wn * 32 + (lane >> 2);
            uint32_t a[4][4], b[4][2];
            #pragma unroll
            for (int i = 0; i < 4; i++) {
                a[i][0] = __float_as_uint(As[kq][r0 + i * 16]);
                a[i][1] = __float_as_uint(As[kq][r0 + i * 16 + 8]);
                a[i][2] = __float_as_uint(As[kq + 4][r0 + i * 16]);
                a[i][3] = __float_as_uint(As[kq + 4][r0 + i * 16 + 8]);
            }
            #pragma unroll
            for (int j = 0; j < 4; j++) {
                b[j][0] = __float_as_uint(Bs[kq][c0 + j * 8]);
                b[j][1] = __float_as_uint(Bs[kq + 4][c0 + j * 8]);
            }
            #pragma unroll
            for (int i = 0; i < 4; i++)
                #pragma unroll
                for (int j = 0; j < 4; j++)
                    mma8(acc[i][j], a[i], b[j]);
        }
        __syncthreads();
    }

    // epilogue: acc -> C (+bias)(+Res), float2 stores (c0/c1 are adjacent cols)
    #pragma unroll
    for (int i = 0; i < 4; i++) {
        int r = by * 128 + wm * 64 + i * 16 + (lane >> 2);
        #pragma unroll
        for (int j = 0; j < 4; j++) {
            int c = bx * 128 + wn * 32 + j * 8 + ((lane & 3) << 1);
            float bx0 = 0.0f, bx1 = 0.0f;
            if (bias) {
                float2 bb = *(const float2*)(bias + c);
                bx0 = bb.x; bx1 = bb.y;
            }
            float2 lo, hi;
            lo.x = acc[i][j][0] + bx0; lo.y = acc[i][j][1] + bx1;
            hi.x = acc[i][j][2] + bx0; hi.y = acc[i][j][3] + bx1;
            if (Res) {
                float2 r0v = *(const float2*)(Res + (size_t)r * N + c);
                float2 r1v = *(const float2*)(Res + (size_t)(r + 8) * N + c);
                lo.x += r0v.x; lo.y += r0v.y;
                hi.x += r1v.x; hi.y += r1v.y;
            }
            *(float2*)(C + (size_t)r * N + c)       = lo;
            *(float2*)(C + (size_t)(r + 8) * N + c) = hi;
        }
    }
}

// ---------------------------------------------------------------------------
// rmsnorm: one block per token, 256 threads, float4 per thread
// ---------------------------------------------------------------------------
__global__ void rmsnorm_kernel(const float* __restrict__ x,
                               const float* __restrict__ gamma,
                               float* __restrict__ h) {
    int t = blockIdx.x;
    int tid = threadIdx.x;
    const float4* xr = (const float4*)(x + (size_t)t * DMODEL);
    float4 v = xr[tid];
    float ss = v.x * v.x + v.y * v.y + v.z * v.z + v.w * v.w;
    #pragma unroll
    for (int o = 16; o; o >>= 1) ss += __shfl_xor_sync(0xffffffffu, ss, o);
    __shared__ float sred[8];
    if ((tid & 31) == 0) sred[tid >> 5] = ss;
    __syncthreads();
    if (tid < 8) {
        float s = sred[tid];
        #pragma unroll
        for (int o = 4; o; o >>= 1) s += __shfl_xor_sync(0xffu, s, o);
        if (tid == 0) sred[0] = s;
    }
    __syncthreads();
    float inv = rsqrtf(sred[0] * (1.0f / DMODEL) + EPS);
    float4 g = ((const float4*)gamma)[tid];
    float4 o;
    o.x = g.x * v.x * inv; o.y = g.y * v.y * inv;
    o.z = g.z * v.z * inv; o.w = g.w * v.w * inv;
    ((float4*)(h + (size_t)t * DMODEL))[tid] = o;
}

// ---------------------------------------------------------------------------
// Tiled SGEMM (fp32 SIMT) - used for the two small GEMMs (down, kv-up)
// ---------------------------------------------------------------------------
template <int BM, int BN, int BK, int TM, int TN>
__global__ void __launch_bounds__((BM / TM) * (BN / TN))
sgemm_bias(const float* __restrict__ A,
           const float* __restrict__ Bm,
           const float* __restrict__ bias,
           const float* __restrict__ Res,
           float* __restrict__ C,
           int M, int N, int K) {
    constexpr int THREADS = (BM / TM) * (BN / TN);
    __shared__ float As[BK][BM];
    __shared__ float Bs[BK][BN];
    int bx = blockIdx.x, by = blockIdx.y;
    int tid = threadIdx.x;
    int tx = tid % (BN / TN);
    int ty = tid / (BN / TN);

    const float* Ablk = A + (size_t)by * BM * K;
    const float* Bblk = Bm + (size_t)bx * BN;

    float acc[TM][TN];
    #pragma unroll
    for (int i = 0; i < TM; i++)
        #pragma unroll
        for (int j = 0; j < TN; j++) acc[i][j] = 0.0f;

    constexpr int A_ITERS = BM * BK / (THREADS * 4);
    constexpr int B_ITERS = BK * BN / (THREADS * 4);

    for (int k0 = 0; k0 < K; k0 += BK) {
        #pragma unroll
        for (int it = 0; it < A_ITERS; ++it) {
            int idx = (tid + it * THREADS) * 4;
            int row = idx / BK, col = idx % BK;
            float4 v = *(const float4*)(Ablk + (size_t)row * K + k0 + col);
            As[col + 0][row] = v.x; As[col + 1][row] = v.y;
            As[col + 2][row] = v.z; As[col + 3][row] = v.w;
        }
        #pragma unroll
        for (int it = 0; it < B_ITERS; ++it) {
            int idx = (tid + it * THREADS) * 4;
            int row = idx / BN, col = idx % BN;
            *(float4*)(&Bs[row][col]) =
                *(const float4*)(Bblk + (size_t)(k0 + row) * N + col);
        }
        __syncthreads();
        #pragma unroll
        for (int k = 0; k < BK; k++) {
            float ar[TM], br[TN];
            #pragma unroll
            for (int i = 0; i < TM; i += 4)
                *(float4*)&ar[i] = *(float4*)&As[k][ty * TM + i];
            #pragma unroll
            for (int j = 0; j < TN; j += 4)
                *(float4*)&br[j] = *(float4*)&Bs[k][tx * TN + j];
            #pragma unroll
            for (int i = 0; i < TM; i++)
                #pragma unroll
                for (int j = 0; j < TN; j++)
                    acc[i][j] = fmaf(ar[i], br[j], acc[i][j]);
        }
        __syncthreads();
    }

    #pragma unroll
    for (int i = 0; i < TM; i++) {
        int row = by * BM + ty * TM + i;
        #pragma unroll
        for (int j = 0; j < TN; j += 4) {
            int col = bx * BN + tx * TN + j;
            float4 bsv = *(const float4*)(bias + col);
            float4 r;
            r.x = acc[i][j + 0] + bsv.x;
            r.y = acc[i][j + 1] + bsv.y;
            r.z = acc[i][j + 2] + bsv.z;
            r.w = acc[i][j + 3] + bsv.w;
            if (Res) {
                float4 rr = *(const float4*)(Res + (size_t)row * N + col);
                r.x += rr.x; r.y += rr.y; r.z += rr.z; r.w += rr.w;
            }
            *(float4*)(C + (size_t)row * N + col) = r;
        }
    }
}

// ---------------------------------------------------------------------------
// Per-token head-mixing attention. One block (256 thr) per token.
// ---------------------------------------------------------------------------
__global__ void attn_kernel(const float* __restrict__ q,
                            const float* __restrict__ kv,
                            float* __restrict__ out) {
    int t = blockIdx.x;
    int tid = threadIdx.x;
    __shared__ float sq[DMODEL];
    __shared__ float skv[2 * DMODEL];
    __shared__ float sp[NHEAD * NHEAD];

    ((float4*)sq)[tid] = ((const float4*)(q + (size_t)t * DMODEL))[tid];
    ((float4*)skv)[tid]       = ((const float4*)(kv + (size_t)t * 2 * DMODEL))[tid];
    ((float4*)skv)[tid + 256] = ((const float4*)(kv + (size_t)t * 2 * DMODEL))[tid + 256];
    __syncthreads();

    {
        int h = tid >> 4, g = tid & 15;
        const float* qh = sq + h * HDIM;
        const float* kg = skv + g * 2 * HDIM;
        float s = 0.0f;
        #pragma unroll
        for (int d = 0; d < HDIM; d++) s = fmaf(qh[d], kg[d], s);
        sp[tid] = s * 0.125f;  // 1/sqrt(64)
    }
    __syncthreads();

    if (tid < NHEAD) {
        float mx = -1e30f;
        #pragma unroll
        for (int g = 0; g < NHEAD; g++) mx = fmaxf(mx, sp[tid * NHEAD + g]);
        float sum = 0.0f;
        #pragma unroll
        for (int g = 0; g < NHEAD; g++) {
            float e = expf(sp[tid * NHEAD + g] - mx);
            sp[tid * NHEAD + g] = e;
            sum += e;
        }
        float invs = 1.0f / sum;
        #pragma unroll
        for (int g = 0; g < NHEAD; g++) sp[tid * NHEAD + g] *= invs;
    }
    __syncthreads();

    #pragma unroll
    for (int r = 0; r < 4; r++) {
        int o = tid + r * 256;
        int h = o >> 6, dd = o & 63;
        float acc = 0.0f;
        #pragma unroll
        for (int g = 0; g < NHEAD; g++)
            acc = fmaf(sp[h * NHEAD + g], skv[g * 2 * HDIM + HDIM + dd], acc);
        out[(size_t)t * DMODEL + o] = acc;
    }
}

// ---------------------------------------------------------------------------
// Fused rmsnorm2 + gate softmax. One block (256 thr) per token.
// ---------------------------------------------------------------------------
__global__ void rms2_gate_kernel(const float* __restrict__ x1,
                                 const float* __restrict__ gamma,
                                 const float* __restrict__ Wg,
                                 const float* __restrict__ bg,
                                 float* __restrict__ h2,
                                 float* __restrict__ gate) {
    int t = blockIdx.x;
    int tid = threadIdx.x;
    float4 v = ((const float4*)(x1 + (size_t)t * DMODEL))[tid];
    float ss = v.x * v.x + v.y * v.y + v.z * v.z + v.w * v.w;
    #pragma unroll
    for (int o = 16; o; o >>= 1) ss += __shfl_xor_sync(0xffffffffu, ss, o);
    __shared__ float sred[8];
    __shared__ float swred[8][NEXP];
    __shared__ float slog[NEXP];
    if ((tid & 31) == 0) sred[tid >> 5] = ss;
    __syncthreads();
    if (tid < 8) {
        float s = sred[tid];
        #pragma unroll
        for (int o = 4; o; o >>= 1) s += __shfl_xor_sync(0xffu, s, o);
        if (tid == 0) sred[0] = s;
    }
    __syncthreads();
    float inv = rsqrtf(sred[0] * (1.0f / DMODEL) + EPS);
    float4 g = ((const float4*)gamma)[tid];
    float4 hv;
    hv.x = g.x * v.x * inv; hv.y = g.y * v.y * inv;
    hv.z = g.z * v.z * inv; hv.w = g.w * v.w * inv;
    ((float4*)(h2 + (size_t)t * DMODEL))[tid] = hv;

    int d0 = tid * 4;
    float pe[NEXP];
    #pragma unroll
    for (int e = 0; e < NEXP; e++) {
        pe[e] = hv.x * Wg[(d0 + 0) * NEXP + e]
              + hv.y * Wg[(d0 + 1) * NEXP + e]
              + hv.z * Wg[(d0 + 2) * NEXP + e]
              + hv.w * Wg[(d0 + 3) * NEXP + e];
    }
    #pragma unroll
    for (int e = 0; e < NEXP; e++)
        #pragma unroll
        for (int o = 16; o; o >>= 1)
            pe[e] += __shfl_xor_sync(0xffffffffu, pe[e], o);
    if ((tid & 31) == 0)
        #pragma unroll
        for (int e = 0; e < NEXP; e++) swred[tid >> 5][e] = pe[e];
    __syncthreads();
    if (tid < NEXP) {
        float lg = bg[tid];
        #pragma unroll
        for (int w = 0; w < 8; w++) lg += swred[w][tid];
        slog[tid] = lg;
    }
    __syncthreads();
    if (tid < NEXP) {
        float mx = slog[0];
        #pragma unroll
        for (int e = 1; e < NEXP; e++) mx = fmaxf(mx, slog[e]);
        float sum = 0.0f;
        #pragma unroll
        for (int e = 0; e < NEXP; e++) sum += expf(slog[e] - mx);
        gate[(size_t)t * NEXP + tid] = expf(slog[tid] - mx) / sum;
    }
}

// ---------------------------------------------------------------------------
// launch
// ---------------------------------------------------------------------------
extern "C" void kernel_launch(void* const* d_in, const int* in_sizes, int n_in,
                              void* d_out, int out_size) {
    const float* x      = (const float*)d_in[0];
    const float* gamma1 = (const float*)d_in[1];
    const float* Wq     = (const float*)d_in[2];
    const float* bq     = (const float*)d_in[3];
    const float* Wdown  = (const float*)d_in[4];
    const float* bdown  = (const float*)d_in[5];
    const float* Wup    = (const float*)d_in[6];
    const float* bup    = (const float*)d_in[7];
    const float* Wo     = (const float*)d_in[8];
    const float* bo     = (const float*)d_in[9];
    const float* gamma2 = (const float*)d_in[10];
    const float* Wg     = (const float*)d_in[11];
    const float* bg     = (const float*)d_in[12];
    const float* We     = (const float*)d_in[13];
    float* out = (float*)d_out;

    float *h, *q, *dl, *kv, *att, *x1, *h2, *gate;
    cudaGetSymbolAddress((void**)&h,    g_h);
    cudaGetSymbolAddress((void**)&q,    g_q);
    cudaGetSymbolAddress((void**)&dl,   g_dl);
    cudaGetSymbolAddress((void**)&kv,   g_kv);
    cudaGetSymbolAddress((void**)&att,  g_att);
    cudaGetSymbolAddress((void**)&x1,   g_x1);
    cudaGetSymbolAddress((void**)&h2,   g_h2);
    cudaGetSymbolAddress((void**)&gate, g_gate);

    // 1. h = rmsnorm(x, gamma1)
    rmsnorm_kernel<<<MTOK, 256>>>(x, gamma1, h);

    // 2. q = h @ Wq + bq           (tf32 tensor cores)
    {
        dim3 grid(DMODEL / 128, MTOK / 128);
        tf32_gemm<0><<<grid, 256>>>(h, nullptr, Wq, bq, nullptr, q,
                                    MTOK, DMODEL, DMODEL);
    }
    // 3. dl = h @ Wdown + bdown    [8192,1024] x [1024,64]  (SIMT)
    {
        dim3 grid(DLAT / 64, MTOK / 64);
        sgemm_bias<64, 64, 16, 4, 4><<<grid, 256>>>(h, Wdown, bdown, nullptr, dl,
                                                    MTOK, DLAT, DMODEL);
    }
    // 4. kv = dl @ Wup + bup       [8192,64] x [64,2048]  (SIMT, mem-bound)
    {
        dim3 grid(2 * DMODEL / 128, MTOK / 128);
        sgemm_bias<128, 128, 8, 8, 8><<<grid, 256>>>(dl, Wup, bup, nullptr, kv,
                                                     MTOK, 2 * DMODEL, DLAT);
    }
    // 5. per-token head-mixing attention
    attn_kernel<<<MTOK, 256>>>(q, kv, att);

    // 6. x1 = x + att @ Wo + bo    (tf32 tensor cores)
    {
        dim3 grid(DMODEL / 128, MTOK / 128);
        tf32_gemm<0><<<grid, 256>>>(att, nullptr, Wo, bo, x, x1,
                                    MTOK, DMODEL, DMODEL);
    }
    // 7. h2 = rmsnorm(x1, gamma2); gate = softmax(h2 @ Wg + bg)
    rms2_gate_kernel<<<MTOK, 256>>>(x1, gamma2, Wg, bg, h2, gate);

    // 8. out = x1 + sum_e gate_e * (h2 @ We[e])  as one K=8192 tf32 GEMM
    {
        dim3 grid(DMODEL / 128, MTOK / 128);
        tf32_gemm<1><<<grid, 256>>>(h2, gate, We, nullptr, x1, out,
                                    MTOK, DMODEL, NEXP * DMODEL);
    }
}

// round 6
// speedup vs baseline: 2.0380x; 1.0513x over previous
#include <cuda_runtime.h>
#include <cuda_bf16.h>
#include <math.h>
#include <stdint.h>

// ---------------------------------------------------------------------------
// HydraBlock: B=4 T=2048 D=1024 H=16 HD=64 L=64 E=8   (8192 tokens)
// TF32 tensor-core GEMMs (4-stage cp.async pipeline) for Wq / Wo / MoE.
// ---------------------------------------------------------------------------

#define MTOK   8192
#define DMODEL 1024
#define NHEAD  16
#define HDIM   64
#define DLAT   64
#define NEXP   8
#define EPS    1e-6f

#define STAGES 4
#define ASTR   20                      // smem A row stride (floats), conflict-free
#define BSTR   136                     // smem B row stride (floats), conflict-free
#define A_STG  (128 * ASTR)            // 2560 floats per A stage
#define B_STG  (16 * BSTR)             // 2176 floats per B stage
#define SMEM_BYTES (STAGES * (A_STG + B_STG) * 4)   // 75776

__device__ __align__(16) float g_h[MTOK * DMODEL];
__device__ __align__(16) float g_q[MTOK * DMODEL];
__device__ __align__(16) float g_dl[MTOK * DLAT];
__device__ __align__(16) float g_kv[MTOK * 2 * DMODEL];
__device__ __align__(16) float g_att[MTOK * DMODEL];
__device__ __align__(16) float g_x1[MTOK * DMODEL];
__device__ __align__(16) float g_h2[MTOK * DMODEL];
__device__ __align__(16) float g_gate[MTOK * NEXP];

// ---------------------------------------------------------------------------
// helpers
// ---------------------------------------------------------------------------
__device__ __forceinline__ uint32_t f2tf(float x) {
    uint32_t r;
    asm("cvt.rna.tf32.f32 %0, %1;" : "=r"(r) : "f"(x));
    return r;
}

__device__ __forceinline__ void mma8(float c[4], const uint32_t a[4], const uint32_t b[2]) {
    asm volatile(
        "mma.sync.aligned.m16n8k8.row.col.f32.tf32.tf32.f32 "
        "{%0,%1,%2,%3}, {%4,%5,%6,%7}, {%8,%9}, {%0,%1,%2,%3};"
        : "+f"(c[0]), "+f"(c[1]), "+f"(c[2]), "+f"(c[3])
        : "r"(a[0]), "r"(a[1]), "r"(a[2]), "r"(a[3]), "r"(b[0]), "r"(b[1]));
}

__device__ __forceinline__ void cp16(float* dst, const float* src) {
    uint32_t d = (uint32_t)__cvta_generic_to_shared(dst);
    asm volatile("cp.async.cg.shared.global [%0], [%1], 16;" :: "r"(d), "l"(src) : "memory");
}

// ---------------------------------------------------------------------------
// TF32 GEMM, 4-stage cp.async pipeline.
// C[M,N] = op(A)[M,K] @ B[K,N] (+bias) (+Res)
// MOE=1: K=8192 virtual; Ahat[m, e*1024+d] = gate[m,e]*h2[m,d], gate applied
// in the fragment path (registers), expert constant per 64 K-tiles.
// CTA tile 128x128x16, 8 warps (2x4), warp tile 64x32, m16n8k8 tf32.
// ---------------------------------------------------------------------------
template <int MOE>
__global__ void __launch_bounds__(256, 1)
tf32_gemm(const float* __restrict__ A, const float* __restrict__ gate,
          const float* __restrict__ Bm, const float* __restrict__ bias,
          const float* __restrict__ Res, float* __restrict__ C,
          int M, int N, int K) {
    extern __shared__ float smem[];
    float* sA = smem;                      // [STAGES][128][ASTR]
    float* sB = smem + STAGES * A_STG;     // [STAGES][16][BSTR]

    const int tid  = threadIdx.x;
    const int lane = tid & 31;
    const int wid  = tid >> 5;
    const int wm   = wid & 1;
    const int wn   = wid >> 1;
    const int bx   = blockIdx.x, by = blockIdx.y;

    const int astr = MOE ? DMODEL : K;

    float acc[4][4][4];
    #pragma unroll
    for (int i = 0; i < 4; i++)
        #pragma unroll
        for (int j = 0; j < 4; j++)
            #pragma unroll
            for (int r = 0; r < 4; r++) acc[i][j][r] = 0.0f;

    auto issue = [&](int kt2) {
        const int buf = kt2 % STAGES;
        const int k0  = kt2 * 16;
        const int ac  = MOE ? (k0 & (DMODEL - 1)) : k0;
        float* dA = sA + buf * A_STG;
        float* dB = sB + buf * B_STG;
        #pragma unroll
        for (int it = 0; it < 2; it++) {
            int idx = tid + it * 256;
            int r = idx >> 2, c = (idx & 3) << 2;
            cp16(dA + r * ASTR + c, A + (size_t)(by * 128 + r) * astr + ac + c);
        }
        #pragma unroll
        for (int it = 0; it < 2; it++) {
            int idx = tid + it * 256;
            int kr = idx >> 5, nc = (idx & 31) << 2;
            cp16(dB + kr * BSTR + nc, Bm + (size_t)(k0 + kr) * N + bx * 128 + nc);
        }
        asm volatile("cp.async.commit_group;" ::: "memory");
    };

    const int NT = K / 16;
    #pragma unroll
    for (int s = 0; s < STAGES - 1; s++) issue(s);

    float gr[8];
    #pragma unroll
    for (int i = 0; i < 8; i++) gr[i] = 1.0f;

    for (int kt = 0; kt < NT; kt++) {
        if (MOE && (kt & 63) == 0) {
            int e = kt >> 6;
            #pragma unroll
            for (int i = 0; i < 4; i++) {
                int ra = by * 128 + wm * 64 + (lane >> 2) + i * 16;
                gr[2 * i]     = __ldg(gate + (size_t)ra * NEXP + e);
                gr[2 * i + 1] = __ldg(gate + (size_t)(ra + 8) * NEXP + e);
            }
        }
        asm volatile("cp.async.wait_group 2;" ::: "memory");
        __syncthreads();
        if (kt + STAGES - 1 < NT) issue(kt + STAGES - 1);

        const float* cA = sA + (kt % STAGES) * A_STG;
        const float* cB = sB + (kt % STAGES) * B_STG;

        #pragma unroll
        for (int ks = 0; ks < 2; ks++) {
            const int kq = ks * 8 + (lane & 3);
            const int r0 = wm * 64 + (lane >> 2);
            const int c0 = wn * 32 + (lane >> 2);
            uint32_t a[4][4], b[4][2];
            #pragma unroll
            for (int i = 0; i < 4; i++) {
                int ra = r0 + i * 16;
                float a0 = cA[ra * ASTR + kq];
                float a1 = cA[(ra + 8) * ASTR + kq];
                float a2 = cA[ra * ASTR + kq + 4];
                float a3 = cA[(ra + 8) * ASTR + kq + 4];
                if (MOE) {
                    a0 *= gr[2 * i]; a2 *= gr[2 * i];
                    a1 *= gr[2 * i + 1]; a3 *= gr[2 * i + 1];
                }
                a[i][0] = f2tf(a0); a[i][1] = f2tf(a1);
                a[i][2] = f2tf(a2); a[i][3] = f2tf(a3);
            }
            #pragma unroll
            for (int j = 0; j < 4; j++) {
                b[j][0] = f2tf(cB[kq * BSTR + c0 + j * 8]);
                b[j][1] = f2tf(cB[(kq + 4) * BSTR + c0 + j * 8]);
            }
            #pragma unroll
            for (int i = 0; i < 4; i++)
                #pragma unroll
                for (int j = 0; j < 4; j++)
                    mma8(acc[i][j], a[i], b[j]);
        }
        // next iteration's top __syncthreads protects buffer reuse
    }

    // epilogue (identical mapping to the passing R5 kernel)
    #pragma unroll
    for (int i = 0; i < 4; i++) {
        int r = by * 128 + wm * 64 + i * 16 + (lane >> 2);
        #pragma unroll
        for (int j = 0; j < 4; j++) {
            int c = bx * 128 + wn * 32 + j * 8 + ((lane & 3) << 1);
            float bx0 = 0.0f, bx1 = 0.0f;
            if (bias) {
                float2 bb = *(const float2*)(bias + c);
                bx0 = bb.x; bx1 = bb.y;
            }
            float2 lo, hi;
            lo.x = acc[i][j][0] + bx0; lo.y = acc[i][j][1] + bx1;
            hi.x = acc[i][j][2] + bx0; hi.y = acc[i][j][3] + bx1;
            if (Res) {
                float2 r0v = *(const float2*)(Res + (size_t)r * N + c);
                float2 r1v = *(const float2*)(Res + (size_t)(r + 8) * N + c);
                lo.x += r0v.x; lo.y += r0v.y;
                hi.x += r1v.x; hi.y += r1v.y;
            }
            *(float2*)(C + (size_t)r * N + c)       = lo;
            *(float2*)(C + (size_t)(r + 8) * N + c) = hi;
        }
    }
}

// ---------------------------------------------------------------------------
// rmsnorm: one block per token, 256 threads, float4 per thread
// ---------------------------------------------------------------------------
__global__ void rmsnorm_kernel(const float* __restrict__ x,
                               const float* __restrict__ gamma,
                               float* __restrict__ h) {
    int t = blockIdx.x;
    int tid = threadIdx.x;
    const float4* xr = (const float4*)(x + (size_t)t * DMODEL);
    float4 v = xr[tid];
    float ss = v.x * v.x + v.y * v.y + v.z * v.z + v.w * v.w;
    #pragma unroll
    for (int o = 16; o; o >>= 1) ss += __shfl_xor_sync(0xffffffffu, ss, o);
    __shared__ float sred[8];
    if ((tid & 31) == 0) sred[tid >> 5] = ss;
    __syncthreads();
    if (tid < 8) {
        float s = sred[tid];
        #pragma unroll
        for (int o = 4; o; o >>= 1) s += __shfl_xor_sync(0xffu, s, o);
        if (tid == 0) sred[0] = s;
    }
    __syncthreads();
    float inv = rsqrtf(sred[0] * (1.0f / DMODEL) + EPS);
    float4 g = ((const float4*)gamma)[tid];
    float4 o;
    o.x = g.x * v.x * inv; o.y = g.y * v.y * inv;
    o.z = g.z * v.z * inv; o.w = g.w * v.w * inv;
    ((float4*)(h + (size_t)t * DMODEL))[tid] = o;
}

// ---------------------------------------------------------------------------
// Tiled SGEMM (fp32 SIMT) - small GEMMs (down, kv-up)
// ---------------------------------------------------------------------------
template <int BM, int BN, int BK, int TM, int TN>
__global__ void __launch_bounds__((BM / TM) * (BN / TN))
sgemm_bias(const float* __restrict__ A,
           const float* __restrict__ Bm,
           const float* __restrict__ bias,
           const float* __restrict__ Res,
           float* __restrict__ C,
           int M, int N, int K) {
    constexpr int THREADS = (BM / TM) * (BN / TN);
    __shared__ float As[BK][BM];
    __shared__ float Bs[BK][BN];
    int bx = blockIdx.x, by = blockIdx.y;
    int tid = threadIdx.x;
    int tx = tid % (BN / TN);
    int ty = tid / (BN / TN);

    const float* Ablk = A + (size_t)by * BM * K;
    const float* Bblk = Bm + (size_t)bx * BN;

    float acc[TM][TN];
    #pragma unroll
    for (int i = 0; i < TM; i++)
        #pragma unroll
        for (int j = 0; j < TN; j++) acc[i][j] = 0.0f;

    constexpr int A_ITERS = BM * BK / (THREADS * 4);
    constexpr int B_ITERS = BK * BN / (THREADS * 4);

    for (int k0 = 0; k0 < K; k0 += BK) {
        #pragma unroll
        for (int it = 0; it < A_ITERS; ++it) {
            int idx = (tid + it * THREADS) * 4;
            int row = idx / BK, col = idx % BK;
            float4 v = *(const float4*)(Ablk + (size_t)row * K + k0 + col);
            As[col + 0][row] = v.x; As[col + 1][row] = v.y;
            As[col + 2][row] = v.z; As[col + 3][row] = v.w;
        }
        #pragma unroll
        for (int it = 0; it < B_ITERS; ++it) {
            int idx = (tid + it * THREADS) * 4;
            int row = idx / BN, col = idx % BN;
            *(float4*)(&Bs[row][col]) =
                *(const float4*)(Bblk + (size_t)(k0 + row) * N + col);
        }
        __syncthreads();
        #pragma unroll
        for (int k = 0; k < BK; k++) {
            float ar[TM], br[TN];
            #pragma unroll
            for (int i = 0; i < TM; i += 4)
                *(float4*)&ar[i] = *(float4*)&As[k][ty * TM + i];
            #pragma unroll
            for (int j = 0; j < TN; j += 4)
                *(float4*)&br[j] = *(float4*)&Bs[k][tx * TN + j];
            #pragma unroll
            for (int i = 0; i < TM; i++)
                #pragma unroll
                for (int j = 0; j < TN; j++)
                    acc[i][j] = fmaf(ar[i], br[j], acc[i][j]);
        }
        __syncthreads();
    }

    #pragma unroll
    for (int i = 0; i < TM; i++) {
        int row = by * BM + ty * TM + i;
        #pragma unroll
        for (int j = 0; j < TN; j += 4) {
            int col = bx * BN + tx * TN + j;
            float4 bsv = *(const float4*)(bias + col);
            float4 r;
            r.x = acc[i][j + 0] + bsv.x;
            r.y = acc[i][j + 1] + bsv.y;
            r.z = acc[i][j + 2] + bsv.z;
            r.w = acc[i][j + 3] + bsv.w;
            if (Res) {
                float4 rr = *(const float4*)(Res + (size_t)row * N + col);
                r.x += rr.x; r.y += rr.y; r.z += rr.z; r.w += rr.w;
            }
            *(float4*)(C + (size_t)row * N + col) = r;
        }
    }
}

// ---------------------------------------------------------------------------
// Per-token head-mixing attention. One block (256 thr) per token.
// ---------------------------------------------------------------------------
__global__ void attn_kernel(const float* __restrict__ q,
                            const float* __restrict__ kv,
                            float* __restrict__ out) {
    int t = blockIdx.x;
    int tid = threadIdx.x;
    __shared__ float sq[DMODEL];
    __shared__ float skv[2 * DMODEL];
    __shared__ float sp[NHEAD * NHEAD];

    ((float4*)sq)[tid] = ((const float4*)(q + (size_t)t * DMODEL))[tid];
    ((float4*)skv)[tid]       = ((const float4*)(kv + (size_t)t * 2 * DMODEL))[tid];
    ((float4*)skv)[tid + 256] = ((const float4*)(kv + (size_t)t * 2 * DMODEL))[tid + 256];
    __syncthreads();

    {
        int h = tid >> 4, g = tid & 15;
        const float* qh = sq + h * HDIM;
        const float* kg = skv + g * 2 * HDIM;
        float s = 0.0f;
        #pragma unroll
        for (int d = 0; d < HDIM; d++) s = fmaf(qh[d], kg[d], s);
        sp[tid] = s * 0.125f;  // 1/sqrt(64)
    }
    __syncthreads();

    if (tid < NHEAD) {
        float mx = -1e30f;
        #pragma unroll
        for (int g = 0; g < NHEAD; g++) mx = fmaxf(mx, sp[tid * NHEAD + g]);
        float sum = 0.0f;
        #pragma unroll
        for (int g = 0; g < NHEAD; g++) {
            float e = expf(sp[tid * NHEAD + g] - mx);
            sp[tid * NHEAD + g] = e;
            sum += e;
        }
        float invs = 1.0f / sum;
        #pragma unroll
        for (int g = 0; g < NHEAD; g++) sp[tid * NHEAD + g] *= invs;
    }
    __syncthreads();

    #pragma unroll
    for (int r = 0; r < 4; r++) {
        int o = tid + r * 256;
        int h = o >> 6, dd = o & 63;
        float acc = 0.0f;
        #pragma unroll
        for (int g = 0; g < NHEAD; g++)
            acc = fmaf(sp[h * NHEAD + g], skv[g * 2 * HDIM + HDIM + dd], acc);
        out[(size_t)t * DMODEL + o] = acc;
    }
}

// ---------------------------------------------------------------------------
// Fused rmsnorm2 + gate softmax. One block (256 thr) per token.
// ---------------------------------------------------------------------------
__global__ void rms2_gate_kernel(const float* __restrict__ x1,
                                 const float* __restrict__ gamma,
                                 const float* __restrict__ Wg,
                                 const float* __restrict__ bg,
                                 float* __restrict__ h2,
                                 float* __restrict__ gate) {
    int t = blockIdx.x;
    int tid = threadIdx.x;
    float4 v = ((const float4*)(x1 + (size_t)t * DMODEL))[tid];
    float ss = v.x * v.x + v.y * v.y + v.z * v.z + v.w * v.w;
    #pragma unroll
    for (int o = 16; o; o >>= 1) ss += __shfl_xor_sync(0xffffffffu, ss, o);
    __shared__ float sred[8];
    __shared__ float swred[8][NEXP];
    __shared__ float slog[NEXP];
    if ((tid & 31) == 0) sred[tid >> 5] = ss;
    __syncthreads();
    if (tid < 8) {
        float s = sred[tid];
        #pragma unroll
        for (int o = 4; o; o >>= 1) s += __shfl_xor_sync(0xffu, s, o);
        if (tid == 0) sred[0] = s;
    }
    __syncthreads();
    float inv = rsqrtf(sred[0] * (1.0f / DMODEL) + EPS);
    float4 g = ((const float4*)gamma)[tid];
    float4 hv;
    hv.x = g.x * v.x * inv; hv.y = g.y * v.y * inv;
    hv.z = g.z * v.z * inv; hv.w = g.w * v.w * inv;
    ((float4*)(h2 + (size_t)t * DMODEL))[tid] = hv;

    int d0 = tid * 4;
    float pe[NEXP];
    #pragma unroll
    for (int e = 0; e < NEXP; e++) {
        pe[e] = hv.x * Wg[(d0 + 0) * NEXP + e]
              + hv.y * Wg[(d0 + 1) * NEXP + e]
              + hv.z * Wg[(d0 + 2) * NEXP + e]
              + hv.w * Wg[(d0 + 3) * NEXP + e];
    }
    #pragma unroll
    for (int e = 0; e < NEXP; e++)
        #pragma unroll
        for (int o = 16; o; o >>= 1)
            pe[e] += __shfl_xor_sync(0xffffffffu, pe[e], o);
    if ((tid & 31) == 0)
        #pragma unroll
        for (int e = 0; e < NEXP; e++) swred[tid >> 5][e] = pe[e];
    __syncthreads();
    if (tid < NEXP) {
        float lg = bg[tid];
        #pragma unroll
        for (int w = 0; w < 8; w++) lg += swred[w][tid];
        slog[tid] = lg;
    }
    __syncthreads();
    if (tid < NEXP) {
        float mx = slog[0];
        #pragma unroll
        for (int e = 1; e < NEXP; e++) mx = fmaxf(mx, slog[e]);
        float sum = 0.0f;
        #pragma unroll
        for (int e = 0; e < NEXP; e++) sum += expf(slog[e] - mx);
        gate[(size_t)t * NEXP + tid] = expf(slog[tid] - mx) / sum;
    }
}

// ---------------------------------------------------------------------------
// launch
// ---------------------------------------------------------------------------
extern "C" void kernel_launch(void* const* d_in, const int* in_sizes, int n_in,
                              void* d_out, int out_size) {
    const float* x      = (const float*)d_in[0];
    const float* gamma1 = (const float*)d_in[1];
    const float* Wq     = (const float*)d_in[2];
    const float* bq     = (const float*)d_in[3];
    const float* Wdown  = (const float*)d_in[4];
    const float* bdown  = (const float*)d_in[5];
    const float* Wup    = (const float*)d_in[6];
    const float* bup    = (const float*)d_in[7];
    const float* Wo     = (const float*)d_in[8];
    const float* bo     = (const float*)d_in[9];
    const float* gamma2 = (const float*)d_in[10];
    const float* Wg     = (const float*)d_in[11];
    const float* bg     = (const float*)d_in[12];
    const float* We     = (const float*)d_in[13];
    float* out = (float*)d_out;

    float *h, *q, *dl, *kv, *att, *x1, *h2, *gate;
    cudaGetSymbolAddress((void**)&h,    g_h);
    cudaGetSymbolAddress((void**)&q,    g_q);
    cudaGetSymbolAddress((void**)&dl,   g_dl);
    cudaGetSymbolAddress((void**)&kv,   g_kv);
    cudaGetSymbolAddress((void**)&att,  g_att);
    cudaGetSymbolAddress((void**)&x1,   g_x1);
    cudaGetSymbolAddress((void**)&h2,   g_h2);
    cudaGetSymbolAddress((void**)&gate, g_gate);

    cudaFuncSetAttribute(tf32_gemm<0>, cudaFuncAttributeMaxDynamicSharedMemorySize, SMEM_BYTES);
    cudaFuncSetAttribute(tf32_gemm<1>, cudaFuncAttributeMaxDynamicSharedMemorySize, SMEM_BYTES);

    // 1. h = rmsnorm(x, gamma1)
    rmsnorm_kernel<<<MTOK, 256>>>(x, gamma1, h);

    // 2. q = h @ Wq + bq           (tf32 pipelined)
    {
        dim3 grid(DMODEL / 128, MTOK / 128);
        tf32_gemm<0><<<grid, 256, SMEM_BYTES>>>(h, nullptr, Wq, bq, nullptr, q,
                                                MTOK, DMODEL, DMODEL);
    }
    // 3. dl = h @ Wdown + bdown    (SIMT)
    {
        dim3 grid(DLAT / 64, MTOK / 64);
        sgemm_bias<64, 64, 16, 4, 4><<<grid, 256>>>(h, Wdown, bdown, nullptr, dl,
                                                    MTOK, DLAT, DMODEL);
    }
    // 4. kv = dl @ Wup + bup       (SIMT, mem-bound)
    {
        dim3 grid(2 * DMODEL / 128, MTOK / 128);
        sgemm_bias<128, 128, 8, 8, 8><<<grid, 256>>>(dl, Wup, bup, nullptr, kv,
                                                     MTOK, 2 * DMODEL, DLAT);
    }
    // 5. per-token head-mixing attention
    attn_kernel<<<MTOK, 256>>>(q, kv, att);

    // 6. x1 = x + att @ Wo + bo    (tf32 pipelined)
    {
        dim3 grid(DMODEL / 128, MTOK / 128);
        tf32_gemm<0><<<grid, 256, SMEM_BYTES>>>(att, nullptr, Wo, bo, x, x1,
                                                MTOK, DMODEL, DMODEL);
    }
    // 7. h2 = rmsnorm(x1, gamma2); gate = softmax(h2 @ Wg + bg)
    rms2_gate_kernel<<<MTOK, 256>>>(x1, gamma2, Wg, bg, h2, gate);

    // 8. out = x1 + sum_e gate_e * (h2 @ We[e])  as one K=8192 tf32 GEMM
    {
        dim3 grid(DMODEL / 128, MTOK / 128);
        tf32_gemm<1><<<grid, 256, SMEM_BYTES>>>(h2, gate, We, nullptr, x1, out,
                                                MTOK, DMODEL, NEXP * DMODEL);
    }
}

// round 7
// speedup vs baseline: 2.2176x; 1.0881x over previous
#include <cuda_runtime.h>
#include <cuda_bf16.h>
#include <math.h>
#include <stdint.h>

// ---------------------------------------------------------------------------
// HydraBlock: B=4 T=2048 D=1024 H=16 HD=64 L=64 E=8   (8192 tokens)
// TF32 tensor-core GEMMs, 4-stage cp.async pipeline, NO converts in the
// hot loop: weights pre-rounded to tf32 per launch, activations rounded
// at the producer kernels.
// ---------------------------------------------------------------------------

#define MTOK   8192
#define DMODEL 1024
#define NHEAD  16
#define HDIM   64
#define DLAT   64
#define NEXP   8
#define EPS    1e-6f

#define STAGES 4
#define ASTR   20
#define BSTR   136
#define A_STG  (128 * ASTR)
#define B_STG  (16 * BSTR)
#define SMEM_BYTES (STAGES * (A_STG + B_STG) * 4)   // 75776

__device__ __align__(16) float g_h[MTOK * DMODEL];
__device__ __align__(16) float g_q[MTOK * DMODEL];
__device__ __align__(16) float g_dl[MTOK * DLAT];
__device__ __align__(16) float g_kv[MTOK * 2 * DMODEL];
__device__ __align__(16) float g_att[MTOK * DMODEL];
__device__ __align__(16) float g_x1[MTOK * DMODEL];
__device__ __align__(16) float g_h2[MTOK * DMODEL];
__device__ __align__(16) float g_gate[MTOK * NEXP];
// tf32-rounded weights
__device__ __align__(16) float g_wq_t[DMODEL * DMODEL];
__device__ __align__(16) float g_wo_t[DMODEL * DMODEL];
__device__ __align__(16) float g_we_t[NEXP * DMODEL * DMODEL];

// ---------------------------------------------------------------------------
// helpers
// ---------------------------------------------------------------------------
__device__ __forceinline__ uint32_t f2tf(float x) {
    uint32_t r;
    asm("cvt.rna.tf32.f32 %0, %1;" : "=r"(r) : "f"(x));
    return r;
}
__device__ __forceinline__ float f2tff(float x) { return __uint_as_float(f2tf(x)); }

__device__ __forceinline__ void mma8(float c[4], const uint32_t a[4], const uint32_t b[2]) {
    asm volatile(
        "mma.sync.aligned.m16n8k8.row.col.f32.tf32.tf32.f32 "
        "{%0,%1,%2,%3}, {%4,%5,%6,%7}, {%8,%9}, {%0,%1,%2,%3};"
        : "+f"(c[0]), "+f"(c[1]), "+f"(c[2]), "+f"(c[3])
        : "r"(a[0]), "r"(a[1]), "r"(a[2]), "r"(a[3]), "r"(b[0]), "r"(b[1]));
}

__device__ __forceinline__ void cp16(float* dst, const float* src) {
    uint32_t d = (uint32_t)__cvta_generic_to_shared(dst);
    asm volatile("cp.async.cg.shared.global [%0], [%1], 16;" :: "r"(d), "l"(src) : "memory");
}

// round fp32 (already gate-scaled) to tf32 by add-then-truncate; HW mma
// truncates the low 13 bits, so +0x1000 implements round-half-up.
__device__ __forceinline__ uint32_t rnd_tf(float x) {
    return __float_as_uint(x) + 0x1000u;
}

// ---------------------------------------------------------------------------
// elementwise tf32 rounding (weights pre-pass), float4 per thread
// ---------------------------------------------------------------------------
__global__ void tf32_round_kernel(const float* __restrict__ in,
                                  float* __restrict__ out) {
    int i = blockIdx.x * blockDim.x + threadIdx.x;
    float4 v = ((const float4*)in)[i];
    v.x = f2tff(v.x); v.y = f2tff(v.y); v.z = f2tff(v.z); v.w = f2tff(v.w);
    ((float4*)out)[i] = v;
}

// ---------------------------------------------------------------------------
// TF32 GEMM, 4-stage cp.async pipeline; operands pre-rounded to tf32.
// MOE=1: K=8192 virtual; A fragment scaled by gate then re-rounded (IADD).
// ---------------------------------------------------------------------------
template <int MOE>
__global__ void __launch_bounds__(256, 1)
tf32_gemm(const float* __restrict__ A, const float* __restrict__ gate,
          const float* __restrict__ Bm, const float* __restrict__ bias,
          const float* __restrict__ Res, float* __restrict__ C,
          int M, int N, int K) {
    extern __shared__ float smem[];
    float* sA = smem;
    float* sB = smem + STAGES * A_STG;

    const int tid  = threadIdx.x;
    const int lane = tid & 31;
    const int wid  = tid >> 5;
    const int wm   = wid & 1;
    const int wn   = wid >> 1;
    const int bx   = blockIdx.x, by = blockIdx.y;

    const int astr = MOE ? DMODEL : K;

    float acc[4][4][4];
    #pragma unroll
    for (int i = 0; i < 4; i++)
        #pragma unroll
        for (int j = 0; j < 4; j++)
            #pragma unroll
            for (int r = 0; r < 4; r++) acc[i][j][r] = 0.0f;

    auto issue = [&](int kt2) {
        const int buf = kt2 % STAGES;
        const int k0  = kt2 * 16;
        const int ac  = MOE ? (k0 & (DMODEL - 1)) : k0;
        float* dA = sA + buf * A_STG;
        float* dB = sB + buf * B_STG;
        #pragma unroll
        for (int it = 0; it < 2; it++) {
            int idx = tid + it * 256;
            int r = idx >> 2, c = (idx & 3) << 2;
            cp16(dA + r * ASTR + c, A + (size_t)(by * 128 + r) * astr + ac + c);
        }
        #pragma unroll
        for (int it = 0; it < 2; it++) {
            int idx = tid + it * 256;
            int kr = idx >> 5, nc = (idx & 31) << 2;
            cp16(dB + kr * BSTR + nc, Bm + (size_t)(k0 + kr) * N + bx * 128 + nc);
        }
        asm volatile("cp.async.commit_group;" ::: "memory");
    };

    const int NT = K / 16;
    #pragma unroll
    for (int s = 0; s < STAGES - 1; s++) issue(s);

    float gr[8];
    #pragma unroll
    for (int i = 0; i < 8; i++) gr[i] = 1.0f;

    for (int kt = 0; kt < NT; kt++) {
        if (MOE && (kt & 63) == 0) {
            int e = kt >> 6;
            #pragma unroll
            for (int i = 0; i < 4; i++) {
                int ra = by * 128 + wm * 64 + (lane >> 2) + i * 16;
                gr[2 * i]     = __ldg(gate + (size_t)ra * NEXP + e);
                gr[2 * i + 1] = __ldg(gate + (size_t)(ra + 8) * NEXP + e);
            }
        }
        asm volatile("cp.async.wait_group 2;" ::: "memory");
        __syncthreads();
        if (kt + STAGES - 1 < NT) issue(kt + STAGES - 1);

        const float* cA = sA + (kt % STAGES) * A_STG;
        const float* cB = sB + (kt % STAGES) * B_STG;

        #pragma unroll
        for (int ks = 0; ks < 2; ks++) {
            const int kq = ks * 8 + (lane & 3);
            const int r0 = wm * 64 + (lane >> 2);
            const int c0 = wn * 32 + (lane >> 2);
            uint32_t a[4][4], b[4][2];
            #pragma unroll
            for (int i = 0; i < 4; i++) {
                int ra = r0 + i * 16;
                float a0 = cA[ra * ASTR + kq];
                float a1 = cA[(ra + 8) * ASTR + kq];
                float a2 = cA[ra * ASTR + kq + 4];
                float a3 = cA[(ra + 8) * ASTR + kq + 4];
                if (MOE) {
                    a[i][0] = rnd_tf(a0 * gr[2 * i]);
                    a[i][1] = rnd_tf(a1 * gr[2 * i + 1]);
                    a[i][2] = rnd_tf(a2 * gr[2 * i]);
                    a[i][3] = rnd_tf(a3 * gr[2 * i + 1]);
                } else {
                    a[i][0] = __float_as_uint(a0);
                    a[i][1] = __float_as_uint(a1);
                    a[i][2] = __float_as_uint(a2);
                    a[i][3] = __float_as_uint(a3);
                }
            }
            #pragma unroll
            for (int j = 0; j < 4; j++) {
                b[j][0] = __float_as_uint(cB[kq * BSTR + c0 + j * 8]);
                b[j][1] = __float_as_uint(cB[(kq + 4) * BSTR + c0 + j * 8]);
            }
            #pragma unroll
            for (int i = 0; i < 4; i++)
                #pragma unroll
                for (int j = 0; j < 4; j++)
                    mma8(acc[i][j], a[i], b[j]);
        }
    }

    #pragma unroll
    for (int i = 0; i < 4; i++) {
        int r = by * 128 + wm * 64 + i * 16 + (lane >> 2);
        #pragma unroll
        for (int j = 0; j < 4; j++) {
            int c = bx * 128 + wn * 32 + j * 8 + ((lane & 3) << 1);
            float bx0 = 0.0f, bx1 = 0.0f;
            if (bias) {
                float2 bb = *(const float2*)(bias + c);
                bx0 = bb.x; bx1 = bb.y;
            }
            float2 lo, hi;
            lo.x = acc[i][j][0] + bx0; lo.y = acc[i][j][1] + bx1;
            hi.x = acc[i][j][2] + bx0; hi.y = acc[i][j][3] + bx1;
            if (Res) {
                float2 r0v = *(const float2*)(Res + (size_t)r * N + c);
                float2 r1v = *(const float2*)(Res + (size_t)(r + 8) * N + c);
                lo.x += r0v.x; lo.y += r0v.y;
                hi.x += r1v.x; hi.y += r1v.y;
            }
            *(float2*)(C + (size_t)r * N + c)       = lo;
            *(float2*)(C + (size_t)(r + 8) * N + c) = hi;
        }
    }
}

// ---------------------------------------------------------------------------
// rmsnorm: output rounded to tf32 (consumed by tf32 GEMMs)
// ---------------------------------------------------------------------------
__global__ void rmsnorm_kernel(const float* __restrict__ x,
                               const float* __restrict__ gamma,
                               float* __restrict__ h) {
    int t = blockIdx.x;
    int tid = threadIdx.x;
    const float4* xr = (const float4*)(x + (size_t)t * DMODEL);
    float4 v = xr[tid];
    float ss = v.x * v.x + v.y * v.y + v.z * v.z + v.w * v.w;
    #pragma unroll
    for (int o = 16; o; o >>= 1) ss += __shfl_xor_sync(0xffffffffu, ss, o);
    __shared__ float sred[8];
    if ((tid & 31) == 0) sred[tid >> 5] = ss;
    __syncthreads();
    if (tid < 8) {
        float s = sred[tid];
        #pragma unroll
        for (int o = 4; o; o >>= 1) s += __shfl_xor_sync(0xffu, s, o);
        if (tid == 0) sred[0] = s;
    }
    __syncthreads();
    float inv = rsqrtf(sred[0] * (1.0f / DMODEL) + EPS);
    float4 g = ((const float4*)gamma)[tid];
    float4 o;
    o.x = f2tff(g.x * v.x * inv); o.y = f2tff(g.y * v.y * inv);
    o.z = f2tff(g.z * v.z * inv); o.w = f2tff(g.w * v.w * inv);
    ((float4*)(h + (size_t)t * DMODEL))[tid] = o;
}

// ---------------------------------------------------------------------------
// Tiled SGEMM (fp32 SIMT) - small GEMMs (down, kv-up)
// ---------------------------------------------------------------------------
template <int BM, int BN, int BK, int TM, int TN>
__global__ void __launch_bounds__((BM / TM) * (BN / TN))
sgemm_bias(const float* __restrict__ A,
           const float* __restrict__ Bm,
           const float* __restrict__ bias,
           const float* __restrict__ Res,
           float* __restrict__ C,
           int M, int N, int K) {
    constexpr int THREADS = (BM / TM) * (BN / TN);
    __shared__ float As[BK][BM];
    __shared__ float Bs[BK][BN];
    int bx = blockIdx.x, by = blockIdx.y;
    int tid = threadIdx.x;
    int tx = tid % (BN / TN);
    int ty = tid / (BN / TN);

    const float* Ablk = A + (size_t)by * BM * K;
    const float* Bblk = Bm + (size_t)bx * BN;

    float acc[TM][TN];
    #pragma unroll
    for (int i = 0; i < TM; i++)
        #pragma unroll
        for (int j = 0; j < TN; j++) acc[i][j] = 0.0f;

    constexpr int A_ITERS = BM * BK / (THREADS * 4);
    constexpr int B_ITERS = BK * BN / (THREADS * 4);

    for (int k0 = 0; k0 < K; k0 += BK) {
        #pragma unroll
        for (int it = 0; it < A_ITERS; ++it) {
            int idx = (tid + it * THREADS) * 4;
            int row = idx / BK, col = idx % BK;
            float4 v = *(const float4*)(Ablk + (size_t)row * K + k0 + col);
            As[col + 0][row] = v.x; As[col + 1][row] = v.y;
            As[col + 2][row] = v.z; As[col + 3][row] = v.w;
        }
        #pragma unroll
        for (int it = 0; it < B_ITERS; ++it) {
            int idx = (tid + it * THREADS) * 4;
            int row = idx / BN, col = idx % BN;
            *(float4*)(&Bs[row][col]) =
                *(const float4*)(Bblk + (size_t)(k0 + row) * N + col);
        }
        __syncthreads();
        #pragma unroll
        for (int k = 0; k < BK; k++) {
            float ar[TM], br[TN];
            #pragma unroll
            for (int i = 0; i < TM; i += 4)
                *(float4*)&ar[i] = *(float4*)&As[k][ty * TM + i];
            #pragma unroll
            for (int j = 0; j < TN; j += 4)
                *(float4*)&br[j] = *(float4*)&Bs[k][tx * TN + j];
            #pragma unroll
            for (int i = 0; i < TM; i++)
                #pragma unroll
                for (int j = 0; j < TN; j++)
                    acc[i][j] = fmaf(ar[i], br[j], acc[i][j]);
        }
        __syncthreads();
    }

    #pragma unroll
    for (int i = 0; i < TM; i++) {
        int row = by * BM + ty * TM + i;
        #pragma unroll
        for (int j = 0; j < TN; j += 4) {
            int col = bx * BN + tx * TN + j;
            float4 bsv = *(const float4*)(bias + col);
            float4 r;
            r.x = acc[i][j + 0] + bsv.x;
            r.y = acc[i][j + 1] + bsv.y;
            r.z = acc[i][j + 2] + bsv.z;
            r.w = acc[i][j + 3] + bsv.w;
            if (Res) {
                float4 rr = *(const float4*)(Res + (size_t)row * N + col);
                r.x += rr.x; r.y += rr.y; r.z += rr.z; r.w += rr.w;
            }
            *(float4*)(C + (size_t)row * N + col) = r;
        }
    }
}

// ---------------------------------------------------------------------------
// Per-token head-mixing attention; output rounded to tf32 (feeds Wo gemm)
// ---------------------------------------------------------------------------
__global__ void attn_kernel(const float* __restrict__ q,
                            const float* __restrict__ kv,
                            float* __restrict__ out) {
    int t = blockIdx.x;
    int tid = threadIdx.x;
    __shared__ float sq[DMODEL];
    __shared__ float skv[2 * DMODEL];
    __shared__ float sp[NHEAD * NHEAD];

    ((float4*)sq)[tid] = ((const float4*)(q + (size_t)t * DMODEL))[tid];
    ((float4*)skv)[tid]       = ((const float4*)(kv + (size_t)t * 2 * DMODEL))[tid];
    ((float4*)skv)[tid + 256] = ((const float4*)(kv + (size_t)t * 2 * DMODEL))[tid + 256];
    __syncthreads();

    {
        int h = tid >> 4, g = tid & 15;
        const float* qh = sq + h * HDIM;
        const float* kg = skv + g * 2 * HDIM;
        float s = 0.0f;
        #pragma unroll
        for (int d = 0; d < HDIM; d++) s = fmaf(qh[d], kg[d], s);
        sp[tid] = s * 0.125f;
    }
    __syncthreads();

    if (tid < NHEAD) {
        float mx = -1e30f;
        #pragma unroll
        for (int g = 0; g < NHEAD; g++) mx = fmaxf(mx, sp[tid * NHEAD + g]);
        float sum = 0.0f;
        #pragma unroll
        for (int g = 0; g < NHEAD; g++) {
            float e = expf(sp[tid * NHEAD + g] - mx);
            sp[tid * NHEAD + g] = e;
            sum += e;
        }
        float invs = 1.0f / sum;
        #pragma unroll
        for (int g = 0; g < NHEAD; g++) sp[tid * NHEAD + g] *= invs;
    }
    __syncthreads();

    #pragma unroll
    for (int r = 0; r < 4; r++) {
        int o = tid + r * 256;
        int h = o >> 6, dd = o & 63;
        float acc = 0.0f;
        #pragma unroll
        for (int g = 0; g < NHEAD; g++)
            acc = fmaf(sp[h * NHEAD + g], skv[g * 2 * HDIM + HDIM + dd], acc);
        out[(size_t)t * DMODEL + o] = f2tff(acc);
    }
}

// ---------------------------------------------------------------------------
// Fused rmsnorm2 + gate softmax; h2 rounded to tf32 at write, gate logits
// computed from unrounded values.
// ---------------------------------------------------------------------------
__global__ void rms2_gate_kernel(const float* __restrict__ x1,
                                 const float* __restrict__ gamma,
                                 const float* __restrict__ Wg,
                                 const float* __restrict__ bg,
                                 float* __restrict__ h2,
                                 float* __restrict__ gate) {
    int t = blockIdx.x;
    int tid = threadIdx.x;
    float4 v = ((const float4*)(x1 + (size_t)t * DMODEL))[tid];
    float ss = v.x * v.x + v.y * v.y + v.z * v.z + v.w * v.w;
    #pragma unroll
    for (int o = 16; o; o >>= 1) ss += __shfl_xor_sync(0xffffffffu, ss, o);
    __shared__ float sred[8];
    __shared__ float swred[8][NEXP];
    __shared__ float slog[NEXP];
    if ((tid & 31) == 0) sred[tid >> 5] = ss;
    __syncthreads();
    if (tid < 8) {
        float s = sred[tid];
        #pragma unroll
        for (int o = 4; o; o >>= 1) s += __shfl_xor_sync(0xffu, s, o);
        if (tid == 0) sred[0] = s;
    }
    __syncthreads();
    float inv = rsqrtf(sred[0] * (1.0f / DMODEL) + EPS);
    float4 g = ((const float4*)gamma)[tid];
    float4 hv;
    hv.x = g.x * v.x * inv; hv.y = g.y * v.y * inv;
    hv.z = g.z * v.z * inv; hv.w = g.w * v.w * inv;
    float4 hr;
    hr.x = f2tff(hv.x); hr.y = f2tff(hv.y); hr.z = f2tff(hv.z); hr.w = f2tff(hv.w);
    ((float4*)(h2 + (size_t)t * DMODEL))[tid] = hr;

    int d0 = tid * 4;
    float pe[NEXP];
    #pragma unroll
    for (int e = 0; e < NEXP; e++) {
        pe[e] = hv.x * Wg[(d0 + 0) * NEXP + e]
              + hv.y * Wg[(d0 + 1) * NEXP + e]
              + hv.z * Wg[(d0 + 2) * NEXP + e]
              + hv.w * Wg[(d0 + 3) * NEXP + e];
    }
    #pragma unroll
    for (int e = 0; e < NEXP; e++)
        #pragma unroll
        for (int o = 16; o; o >>= 1)
            pe[e] += __shfl_xor_sync(0xffffffffu, pe[e], o);
    if ((tid & 31) == 0)
        #pragma unroll
        for (int e = 0; e < NEXP; e++) swred[tid >> 5][e] = pe[e];
    __syncthreads();
    if (tid < NEXP) {
        float lg = bg[tid];
        #pragma unroll
        for (int w = 0; w < 8; w++) lg += swred[w][tid];
        slog[tid] = lg;
    }
    __syncthreads();
    if (tid < NEXP) {
        float mx = slog[0];
        #pragma unroll
        for (int e = 1; e < NEXP; e++) mx = fmaxf(mx, slog[e]);
        float sum = 0.0f;
        #pragma unroll
        for (int e = 0; e < NEXP; e++) sum += expf(slog[e] - mx);
        gate[(size_t)t * NEXP + tid] = expf(slog[tid] - mx) / sum;
    }
}

// ---------------------------------------------------------------------------
// launch
// ---------------------------------------------------------------------------
extern "C" void kernel_launch(void* const* d_in, const int* in_sizes, int n_in,
                              void* d_out, int out_size) {
    const float* x      = (const float*)d_in[0];
    const float* gamma1 = (const float*)d_in[1];
    const float* Wq     = (const float*)d_in[2];
    const float* bq     = (const float*)d_in[3];
    const float* Wdown  = (const float*)d_in[4];
    const float* bdown  = (const float*)d_in[5];
    const float* Wup    = (const float*)d_in[6];
    const float* bup    = (const float*)d_in[7];
    const float* Wo     = (const float*)d_in[8];
    const float* bo     = (const float*)d_in[9];
    const float* gamma2 = (const float*)d_in[10];
    const float* Wg     = (const float*)d_in[11];
    const float* bg     = (const float*)d_in[12];
    const float* We     = (const float*)d_in[13];
    float* out = (float*)d_out;

    float *h, *q, *dl, *kv, *att, *x1, *h2, *gate, *wq_t, *wo_t, *we_t;
    cudaGetSymbolAddress((void**)&h,    g_h);
    cudaGetSymbolAddress((void**)&q,    g_q);
    cudaGetSymbolAddress((void**)&dl,   g_dl);
    cudaGetSymbolAddress((void**)&kv,   g_kv);
    cudaGetSymbolAddress((void**)&att,  g_att);
    cudaGetSymbolAddress((void**)&x1,   g_x1);
    cudaGetSymbolAddress((void**)&h2,   g_h2);
    cudaGetSymbolAddress((void**)&gate, g_gate);
    cudaGetSymbolAddress((void**)&wq_t, g_wq_t);
    cudaGetSymbolAddress((void**)&wo_t, g_wo_t);
    cudaGetSymbolAddress((void**)&we_t, g_we_t);

    cudaFuncSetAttribute(tf32_gemm<0>, cudaFuncAttributeMaxDynamicSharedMemorySize, SMEM_BYTES);
    cudaFuncSetAttribute(tf32_gemm<1>, cudaFuncAttributeMaxDynamicSharedMemorySize, SMEM_BYTES);

    // 0. pre-round weights to tf32 (runs concurrently-ish with stage 1)
    tf32_round_kernel<<<DMODEL * DMODEL / (256 * 4), 256>>>(Wq, wq_t);
    tf32_round_kernel<<<DMODEL * DMODEL / (256 * 4), 256>>>(Wo, wo_t);
    tf32_round_kernel<<<NEXP * DMODEL * DMODEL / (256 * 4), 256>>>(We, we_t);

    // 1. h = rmsnorm(x, gamma1)   (tf32-rounded output)
    rmsnorm_kernel<<<MTOK, 256>>>(x, gamma1, h);

    // 2. q = h @ Wq + bq           (tf32 pipelined, no inner-loop cvt)
    {
        dim3 grid(DMODEL / 128, MTOK / 128);
        tf32_gemm<0><<<grid, 256, SMEM_BYTES>>>(h, nullptr, wq_t, bq, nullptr, q,
                                                MTOK, DMODEL, DMODEL);
    }
    // 3. dl = h @ Wdown + bdown    (SIMT)
    {
        dim3 grid(DLAT / 64, MTOK / 64);
        sgemm_bias<64, 64, 16, 4, 4><<<grid, 256>>>(h, Wdown, bdown, nullptr, dl,
                                                    MTOK, DLAT, DMODEL);
    }
    // 4. kv = dl @ Wup + bup       (SIMT, mem-bound)
    {
        dim3 grid(2 * DMODEL / 128, MTOK / 128);
        sgemm_bias<128, 128, 8, 8, 8><<<grid, 256>>>(dl, Wup, bup, nullptr, kv,
                                                     MTOK, 2 * DMODEL, DLAT);
    }
    // 5. attention (tf32-rounded output)
    attn_kernel<<<MTOK, 256>>>(q, kv, att);

    // 6. x1 = x + att @ Wo + bo    (tf32 pipelined)
    {
        dim3 grid(DMODEL / 128, MTOK / 128);
        tf32_gemm<0><<<grid, 256, SMEM_BYTES>>>(att, nullptr, wo_t, bo, x, x1,
                                                MTOK, DMODEL, DMODEL);
    }
    // 7. h2 = rmsnorm(x1, gamma2) (rounded); gate = softmax(h2 @ Wg + bg)
    rms2_gate_kernel<<<MTOK, 256>>>(x1, gamma2, Wg, bg, h2, gate);

    // 8. out = x1 + sum_e gate_e * (h2 @ We[e])  (tf32, K=8192 virtual)
    {
        dim3 grid(DMODEL / 128, MTOK / 128);
        tf32_gemm<1><<<grid, 256, SMEM_BYTES>>>(h2, gate, we_t, nullptr, x1, out,
                                                MTOK, DMODEL, NEXP * DMODEL);
    }
}

// round 8
// speedup vs baseline: 2.5289x; 1.1404x over previous
#include <cuda_runtime.h>
#include <cuda_bf16.h>
#include <math.h>
#include <stdint.h>

// ---------------------------------------------------------------------------
// HydraBlock: B=4 T=2048 D=1024 H=16 HD=64 L=64 E=8   (8192 tokens)
// TF32 tensor-core GEMMs, 3-stage cp.async pipeline, 2 CTAs/SM.
// Weights pre-rounded to tf32; activations rounded at producers.
// ---------------------------------------------------------------------------

#define MTOK   8192
#define DMODEL 1024
#define NHEAD  16
#define HDIM   64
#define DLAT   64
#define NEXP   8
#define EPS    1e-6f

#define STAGES 3
#define ASTR   20
#define BSTR   136
#define A_STG  (128 * ASTR)
#define B_STG  (16 * BSTR)
#define SMEM_BYTES (STAGES * (A_STG + B_STG) * 4)   // 56832

__device__ __align__(16) float g_h[MTOK * DMODEL];
__device__ __align__(16) float g_q[MTOK * DMODEL];
__device__ __align__(16) float g_dl[MTOK * DLAT];
__device__ __align__(16) float g_kv[MTOK * 2 * DMODEL];
__device__ __align__(16) float g_att[MTOK * DMODEL];
__device__ __align__(16) float g_x1[MTOK * DMODEL];
__device__ __align__(16) float g_h2[MTOK * DMODEL];
__device__ __align__(16) float g_gate[MTOK * NEXP];
__device__ __align__(16) float g_wq_t[DMODEL * DMODEL];
__device__ __align__(16) float g_wo_t[DMODEL * DMODEL];
__device__ __align__(16) float g_we_t[NEXP * DMODEL * DMODEL];

// ---------------------------------------------------------------------------
// helpers
// ---------------------------------------------------------------------------
__device__ __forceinline__ uint32_t f2tf(float x) {
    uint32_t r;
    asm("cvt.rna.tf32.f32 %0, %1;" : "=r"(r) : "f"(x));
    return r;
}
__device__ __forceinline__ float f2tff(float x) { return __uint_as_float(f2tf(x)); }

__device__ __forceinline__ void mma8(float c[4], const uint32_t a[4], const uint32_t b[2]) {
    asm volatile(
        "mma.sync.aligned.m16n8k8.row.col.f32.tf32.tf32.f32 "
        "{%0,%1,%2,%3}, {%4,%5,%6,%7}, {%8,%9}, {%0,%1,%2,%3};"
        : "+f"(c[0]), "+f"(c[1]), "+f"(c[2]), "+f"(c[3])
        : "r"(a[0]), "r"(a[1]), "r"(a[2]), "r"(a[3]), "r"(b[0]), "r"(b[1]));
}

__device__ __forceinline__ void cp16(float* dst, const float* src) {
    uint32_t d = (uint32_t)__cvta_generic_to_shared(dst);
    asm volatile("cp.async.cg.shared.global [%0], [%1], 16;" :: "r"(d), "l"(src) : "memory");
}

// fp32 -> tf32 round-half-up via integer add (mma HW truncates low 13 bits)
__device__ __forceinline__ uint32_t rnd_tf(float x) {
    return __float_as_uint(x) + 0x1000u;
}

// ---------------------------------------------------------------------------
// elementwise tf32 rounding (weights pre-pass)
// ---------------------------------------------------------------------------
__global__ void tf32_round_kernel(const float* __restrict__ in,
                                  float* __restrict__ out) {
    int i = blockIdx.x * blockDim.x + threadIdx.x;
    float4 v = ((const float4*)in)[i];
    v.x = f2tff(v.x); v.y = f2tff(v.y); v.z = f2tff(v.z); v.w = f2tff(v.w);
    ((float4*)out)[i] = v;
}

// ---------------------------------------------------------------------------
// TF32 GEMM, 3-stage cp.async pipeline, 2 CTAs/SM.
// MOE=1: K=8192 virtual; A fragment scaled by gate then re-rounded (IADD).
// ---------------------------------------------------------------------------
template <int MOE>
__global__ void __launch_bounds__(256, 2)
tf32_gemm(const float* __restrict__ A, const float* __restrict__ gate,
          const float* __restrict__ Bm, const float* __restrict__ bias,
          const float* __restrict__ Res, float* __restrict__ C,
          int M, int N, int K) {
    extern __shared__ float smem[];
    float* sA = smem;
    float* sB = smem + STAGES * A_STG;

    const int tid  = threadIdx.x;
    const int lane = tid & 31;
    const int wid  = tid >> 5;
    const int wm   = wid & 1;
    const int wn   = wid >> 1;
    const int bx   = blockIdx.x, by = blockIdx.y;

    const int astr = MOE ? DMODEL : K;

    float acc[4][4][4];
    #pragma unroll
    for (int i = 0; i < 4; i++)
        #pragma unroll
        for (int j = 0; j < 4; j++)
            #pragma unroll
            for (int r = 0; r < 4; r++) acc[i][j][r] = 0.0f;

    auto issue = [&](int kt2) {
        const int buf = kt2 % STAGES;
        const int k0  = kt2 * 16;
        const int ac  = MOE ? (k0 & (DMODEL - 1)) : k0;
        float* dA = sA + buf * A_STG;
        float* dB = sB + buf * B_STG;
        #pragma unroll
        for (int it = 0; it < 2; it++) {
            int idx = tid + it * 256;
            int r = idx >> 2, c = (idx & 3) << 2;
            cp16(dA + r * ASTR + c, A + (size_t)(by * 128 + r) * astr + ac + c);
        }
        #pragma unroll
        for (int it = 0; it < 2; it++) {
            int idx = tid + it * 256;
            int kr = idx >> 5, nc = (idx & 31) << 2;
            cp16(dB + kr * BSTR + nc, Bm + (size_t)(k0 + kr) * N + bx * 128 + nc);
        }
        asm volatile("cp.async.commit_group;" ::: "memory");
    };

    const int NT = K / 16;
    #pragma unroll
    for (int s = 0; s < STAGES - 1; s++) issue(s);

    float gr[8];
    #pragma unroll
    for (int i = 0; i < 8; i++) gr[i] = 1.0f;

    for (int kt = 0; kt < NT; kt++) {
        if (MOE && (kt & 63) == 0) {
            int e = kt >> 6;
            #pragma unroll
            for (int i = 0; i < 4; i++) {
                int ra = by * 128 + wm * 64 + (lane >> 2) + i * 16;
                gr[2 * i]     = __ldg(gate + (size_t)ra * NEXP + e);
                gr[2 * i + 1] = __ldg(gate + (size_t)(ra + 8) * NEXP + e);
            }
        }
        asm volatile("cp.async.wait_group %0;" :: "n"(STAGES - 2) : "memory");
        __syncthreads();
        if (kt + STAGES - 1 < NT) issue(kt + STAGES - 1);

        const float* cA = sA + (kt % STAGES) * A_STG;
        const float* cB = sB + (kt % STAGES) * B_STG;

        #pragma unroll
        for (int ks = 0; ks < 2; ks++) {
            const int kq = ks * 8 + (lane & 3);
            const int r0 = wm * 64 + (lane >> 2);
            const int c0 = wn * 32 + (lane >> 2);
            // B fragments first (8 regs), then stream A per row-block (4 regs)
            uint32_t b[4][2];
            #pragma unroll
            for (int j = 0; j < 4; j++) {
                b[j][0] = __float_as_uint(cB[kq * BSTR + c0 + j * 8]);
                b[j][1] = __float_as_uint(cB[(kq + 4) * BSTR + c0 + j * 8]);
            }
            #pragma unroll
            for (int i = 0; i < 4; i++) {
                int ra = r0 + i * 16;
                uint32_t a[4];
                if (MOE) {
                    a[0] = rnd_tf(cA[ra * ASTR + kq] * gr[2 * i]);
                    a[1] = rnd_tf(cA[(ra + 8) * ASTR + kq] * gr[2 * i + 1]);
                    a[2] = rnd_tf(cA[ra * ASTR + kq + 4] * gr[2 * i]);
                    a[3] = rnd_tf(cA[(ra + 8) * ASTR + kq + 4] * gr[2 * i + 1]);
                } else {
                    a[0] = __float_as_uint(cA[ra * ASTR + kq]);
                    a[1] = __float_as_uint(cA[(ra + 8) * ASTR + kq]);
                    a[2] = __float_as_uint(cA[ra * ASTR + kq + 4]);
                    a[3] = __float_as_uint(cA[(ra + 8) * ASTR + kq + 4]);
                }
                #pragma unroll
                for (int j = 0; j < 4; j++)
                    mma8(acc[i][j], a, b[j]);
            }
        }
    }

    #pragma unroll
    for (int i = 0; i < 4; i++) {
        int r = by * 128 + wm * 64 + i * 16 + (lane >> 2);
        #pragma unroll
        for (int j = 0; j < 4; j++) {
            int c = bx * 128 + wn * 32 + j * 8 + ((lane & 3) << 1);
            float bx0 = 0.0f, bx1 = 0.0f;
            if (bias) {
                float2 bb = *(const float2*)(bias + c);
                bx0 = bb.x; bx1 = bb.y;
            }
            float2 lo, hi;
            lo.x = acc[i][j][0] + bx0; lo.y = acc[i][j][1] + bx1;
            hi.x = acc[i][j][2] + bx0; hi.y = acc[i][j][3] + bx1;
            if (Res) {
                float2 r0v = *(const float2*)(Res + (size_t)r * N + c);
                float2 r1v = *(const float2*)(Res + (size_t)(r + 8) * N + c);
                lo.x += r0v.x; lo.y += r0v.y;
                hi.x += r1v.x; hi.y += r1v.y;
            }
            *(float2*)(C + (size_t)r * N + c)       = lo;
            *(float2*)(C + (size_t)(r + 8) * N + c) = hi;
        }
    }
}

// ---------------------------------------------------------------------------
// rmsnorm: output rounded to tf32
// ---------------------------------------------------------------------------
__global__ void rmsnorm_kernel(const float* __restrict__ x,
                               const float* __restrict__ gamma,
                               float* __restrict__ h) {
    int t = blockIdx.x;
    int tid = threadIdx.x;
    const float4* xr = (const float4*)(x + (size_t)t * DMODEL);
    float4 v = xr[tid];
    float ss = v.x * v.x + v.y * v.y + v.z * v.z + v.w * v.w;
    #pragma unroll
    for (int o = 16; o; o >>= 1) ss += __shfl_xor_sync(0xffffffffu, ss, o);
    __shared__ float sred[8];
    if ((tid & 31) == 0) sred[tid >> 5] = ss;
    __syncthreads();
    if (tid < 8) {
        float s = sred[tid];
        #pragma unroll
        for (int o = 4; o; o >>= 1) s += __shfl_xor_sync(0xffu, s, o);
        if (tid == 0) sred[0] = s;
    }
    __syncthreads();
    float inv = rsqrtf(sred[0] * (1.0f / DMODEL) + EPS);
    float4 g = ((const float4*)gamma)[tid];
    float4 o;
    o.x = f2tff(g.x * v.x * inv); o.y = f2tff(g.y * v.y * inv);
    o.z = f2tff(g.z * v.z * inv); o.w = f2tff(g.w * v.w * inv);
    ((float4*)(h + (size_t)t * DMODEL))[tid] = o;
}

// ---------------------------------------------------------------------------
// Tiled SGEMM (fp32 SIMT) - small GEMMs (down, kv-up)
// ---------------------------------------------------------------------------
template <int BM, int BN, int BK, int TM, int TN>
__global__ void __launch_bounds__((BM / TM) * (BN / TN))
sgemm_bias(const float* __restrict__ A,
           const float* __restrict__ Bm,
           const float* __restrict__ bias,
           const float* __restrict__ Res,
           float* __restrict__ C,
           int M, int N, int K) {
    constexpr int THREADS = (BM / TM) * (BN / TN);
    __shared__ float As[BK][BM];
    __shared__ float Bs[BK][BN];
    int bx = blockIdx.x, by = blockIdx.y;
    int tid = threadIdx.x;
    int tx = tid % (BN / TN);
    int ty = tid / (BN / TN);

    const float* Ablk = A + (size_t)by * BM * K;
    const float* Bblk = Bm + (size_t)bx * BN;

    float acc[TM][TN];
    #pragma unroll
    for (int i = 0; i < TM; i++)
        #pragma unroll
        for (int j = 0; j < TN; j++) acc[i][j] = 0.0f;

    constexpr int A_ITERS = BM * BK / (THREADS * 4);
    constexpr int B_ITERS = BK * BN / (THREADS * 4);

    for (int k0 = 0; k0 < K; k0 += BK) {
        #pragma unroll
        for (int it = 0; it < A_ITERS; ++it) {
            int idx = (tid + it * THREADS) * 4;
            int row = idx / BK, col = idx % BK;
            float4 v = *(const float4*)(Ablk + (size_t)row * K + k0 + col);
            As[col + 0][row] = v.x; As[col + 1][row] = v.y;
            As[col + 2][row] = v.z; As[col + 3][row] = v.w;
        }
        #pragma unroll
        for (int it = 0; it < B_ITERS; ++it) {
            int idx = (tid + it * THREADS) * 4;
            int row = idx / BN, col = idx % BN;
            *(float4*)(&Bs[row][col]) =
                *(const float4*)(Bblk + (size_t)(k0 + row) * N + col);
        }
        __syncthreads();
        #pragma unroll
        for (int k = 0; k < BK; k++) {
            float ar[TM], br[TN];
            #pragma unroll
            for (int i = 0; i < TM; i += 4)
                *(float4*)&ar[i] = *(float4*)&As[k][ty * TM + i];
            #pragma unroll
            for (int j = 0; j < TN; j += 4)
                *(float4*)&br[j] = *(float4*)&Bs[k][tx * TN + j];
            #pragma unroll
            for (int i = 0; i < TM; i++)
                #pragma unroll
                for (int j = 0; j < TN; j++)
                    acc[i][j] = fmaf(ar[i], br[j], acc[i][j]);
        }
        __syncthreads();
    }

    #pragma unroll
    for (int i = 0; i < TM; i++) {
        int row = by * BM + ty * TM + i;
        #pragma unroll
        for (int j = 0; j < TN; j += 4) {
            int col = bx * BN + tx * TN + j;
            float4 bsv = *(const float4*)(bias + col);
            float4 r;
            r.x = acc[i][j + 0] + bsv.x;
            r.y = acc[i][j + 1] + bsv.y;
            r.z = acc[i][j + 2] + bsv.z;
            r.w = acc[i][j + 3] + bsv.w;
            if (Res) {
                float4 rr = *(const float4*)(Res + (size_t)row * N + col);
                r.x += rr.x; r.y += rr.y; r.z += rr.z; r.w += rr.w;
            }
            *(float4*)(C + (size_t)row * N + col) = r;
        }
    }
}

// ---------------------------------------------------------------------------
// Per-token head-mixing attention; output rounded to tf32
// ---------------------------------------------------------------------------
__global__ void attn_kernel(const float* __restrict__ q,
                            const float* __restrict__ kv,
                            float* __restrict__ out) {
    int t = blockIdx.x;
    int tid = threadIdx.x;
    __shared__ float sq[DMODEL];
    __shared__ float skv[2 * DMODEL];
    __shared__ float sp[NHEAD * NHEAD];

    ((float4*)sq)[tid] = ((const float4*)(q + (size_t)t * DMODEL))[tid];
    ((float4*)skv)[tid]       = ((const float4*)(kv + (size_t)t * 2 * DMODEL))[tid];
    ((float4*)skv)[tid + 256] = ((const float4*)(kv + (size_t)t * 2 * DMODEL))[tid + 256];
    __syncthreads();

    {
        int h = tid >> 4, g = tid & 15;
        const float* qh = sq + h * HDIM;
        const float* kg = skv + g * 2 * HDIM;
        float s = 0.0f;
        #pragma unroll
        for (int d = 0; d < HDIM; d++) s = fmaf(qh[d], kg[d], s);
        sp[tid] = s * 0.125f;
    }
    __syncthreads();

    if (tid < NHEAD) {
        float mx = -1e30f;
        #pragma unroll
        for (int g = 0; g < NHEAD; g++) mx = fmaxf(mx, sp[tid * NHEAD + g]);
        float sum = 0.0f;
        #pragma unroll
        for (int g = 0; g < NHEAD; g++) {
            float e = expf(sp[tid * NHEAD + g] - mx);
            sp[tid * NHEAD + g] = e;
            sum += e;
        }
        float invs = 1.0f / sum;
        #pragma unroll
        for (int g = 0; g < NHEAD; g++) sp[tid * NHEAD + g] *= invs;
    }
    __syncthreads();

    #pragma unroll
    for (int r = 0; r < 4; r++) {
        int o = tid + r * 256;
        int h = o >> 6, dd = o & 63;
        float acc = 0.0f;
        #pragma unroll
        for (int g = 0; g < NHEAD; g++)
            acc = fmaf(sp[h * NHEAD + g], skv[g * 2 * HDIM + HDIM + dd], acc);
        out[(size_t)t * DMODEL + o] = f2tff(acc);
    }
}

// ---------------------------------------------------------------------------
// Fused rmsnorm2 + gate softmax; h2 tf32-rounded at write
// ---------------------------------------------------------------------------
__global__ void rms2_gate_kernel(const float* __restrict__ x1,
                                 const float* __restrict__ gamma,
                                 const float* __restrict__ Wg,
                                 const float* __restrict__ bg,
                                 float* __restrict__ h2,
                                 float* __restrict__ gate) {
    int t = blockIdx.x;
    int tid = threadIdx.x;
    float4 v = ((const float4*)(x1 + (size_t)t * DMODEL))[tid];
    float ss = v.x * v.x + v.y * v.y + v.z * v.z + v.w * v.w;
    #pragma unroll
    for (int o = 16; o; o >>= 1) ss += __shfl_xor_sync(0xffffffffu, ss, o);
    __shared__ float sred[8];
    __shared__ float swred[8][NEXP];
    __shared__ float slog[NEXP];
    if ((tid & 31) == 0) sred[tid >> 5] = ss;
    __syncthreads();
    if (tid < 8) {
        float s = sred[tid];
        #pragma unroll
        for (int o = 4; o; o >>= 1) s += __shfl_xor_sync(0xffu, s, o);
        if (tid == 0) sred[0] = s;
    }
    __syncthreads();
    float inv = rsqrtf(sred[0] * (1.0f / DMODEL) + EPS);
    float4 g = ((const float4*)gamma)[tid];
    float4 hv;
    hv.x = g.x * v.x * inv; hv.y = g.y * v.y * inv;
    hv.z = g.z * v.z * inv; hv.w = g.w * v.w * inv;
    float4 hr;
    hr.x = f2tff(hv.x); hr.y = f2tff(hv.y); hr.z = f2tff(hv.z); hr.w = f2tff(hv.w);
    ((float4*)(h2 + (size_t)t * DMODEL))[tid] = hr;

    int d0 = tid * 4;
    float pe[NEXP];
    #pragma unroll
    for (int e = 0; e < NEXP; e++) {
        pe[e] = hv.x * Wg[(d0 + 0) * NEXP + e]
              + hv.y * Wg[(d0 + 1) * NEXP + e]
              + hv.z * Wg[(d0 + 2) * NEXP + e]
              + hv.w * Wg[(d0 + 3) * NEXP + e];
    }
    #pragma unroll
    for (int e = 0; e < NEXP; e++)
        #pragma unroll
        for (int o = 16; o; o >>= 1)
            pe[e] += __shfl_xor_sync(0xffffffffu, pe[e], o);
    if ((tid & 31) == 0)
        #pragma unroll
        for (int e = 0; e < NEXP; e++) swred[tid >> 5][e] = pe[e];
    __syncthreads();
    if (tid < NEXP) {
        float lg = bg[tid];
        #pragma unroll
        for (int w = 0; w < 8; w++) lg += swred[w][tid];
        slog[tid] = lg;
    }
    __syncthreads();
    if (tid < NEXP) {
        float mx = slog[0];
        #pragma unroll
        for (int e = 1; e < NEXP; e++) mx = fmaxf(mx, slog[e]);
        float sum = 0.0f;
        #pragma unroll
        for (int e = 0; e < NEXP; e++) sum += expf(slog[e] - mx);
        gate[(size_t)t * NEXP + tid] = expf(slog[tid] - mx) / sum;
    }
}

// ---------------------------------------------------------------------------
// launch  (order arranged so launch #4 = tf32_gemm<0> for the ncu capture)
// ---------------------------------------------------------------------------
extern "C" void kernel_launch(void* const* d_in, const int* in_sizes, int n_in,
                              void* d_out, int out_size) {
    const float* x      = (const float*)d_in[0];
    const float* gamma1 = (const float*)d_in[1];
    const float* Wq     = (const float*)d_in[2];
    const float* bq     = (const float*)d_in[3];
    const float* Wdown  = (const float*)d_in[4];
    const float* bdown  = (const float*)d_in[5];
    const float* Wup    = (const float*)d_in[6];
    const float* bup    = (const float*)d_in[7];
    const float* Wo     = (const float*)d_in[8];
    const float* bo     = (const float*)d_in[9];
    const float* gamma2 = (const float*)d_in[10];
    const float* Wg     = (const float*)d_in[11];
    const float* bg     = (const float*)d_in[12];
    const float* We     = (const float*)d_in[13];
    float* out = (float*)d_out;

    float *h, *q, *dl, *kv, *att, *x1, *h2, *gate, *wq_t, *wo_t, *we_t;
    cudaGetSymbolAddress((void**)&h,    g_h);
    cudaGetSymbolAddress((void**)&q,    g_q);
    cudaGetSymbolAddress((void**)&dl,   g_dl);
    cudaGetSymbolAddress((void**)&kv,   g_kv);
    cudaGetSymbolAddress((void**)&att,  g_att);
    cudaGetSymbolAddress((void**)&x1,   g_x1);
    cudaGetSymbolAddress((void**)&h2,   g_h2);
    cudaGetSymbolAddress((void**)&gate, g_gate);
    cudaGetSymbolAddress((void**)&wq_t, g_wq_t);
    cudaGetSymbolAddress((void**)&wo_t, g_wo_t);
    cudaGetSymbolAddress((void**)&we_t, g_we_t);

    cudaFuncSetAttribute(tf32_gemm<0>, cudaFuncAttributeMaxDynamicSharedMemorySize, SMEM_BYTES);
    cudaFuncSetAttribute(tf32_gemm<1>, cudaFuncAttributeMaxDynamicSharedMemorySize, SMEM_BYTES);

    // 1. h = rmsnorm(x, gamma1)
    rmsnorm_kernel<<<MTOK, 256>>>(x, gamma1, h);
    // 2-3. weight rounding (Wq + We now; Wo later)
    tf32_round_kernel<<<DMODEL * DMODEL / (256 * 4), 256>>>(Wq, wq_t);
    tf32_round_kernel<<<NEXP * DMODEL * DMODEL / (256 * 4), 256>>>(We, we_t);
    // 4. q = h @ Wq + bq   <-- ncu capture slot
    {
        dim3 grid(DMODEL / 128, MTOK / 128);
        tf32_gemm<0><<<grid, 256, SMEM_BYTES>>>(h, nullptr, wq_t, bq, nullptr, q,
                                                MTOK, DMODEL, DMODEL);
    }
    // 5. dl = h @ Wdown + bdown
    {
        dim3 grid(DLAT / 64, MTOK / 64);
        sgemm_bias<64, 64, 16, 4, 4><<<grid, 256>>>(h, Wdown, bdown, nullptr, dl,
                                                    MTOK, DLAT, DMODEL);
    }
    // 6. kv = dl @ Wup + bup
    {
        dim3 grid(2 * DMODEL / 128, MTOK / 128);
        sgemm_bias<128, 128, 8, 8, 8><<<grid, 256>>>(dl, Wup, bup, nullptr, kv,
                                                     MTOK, 2 * DMODEL, DLAT);
    }
    // 7. attention
    attn_kernel<<<MTOK, 256>>>(q, kv, att);
    // 8. round Wo
    tf32_round_kernel<<<DMODEL * DMODEL / (256 * 4), 256>>>(Wo, wo_t);
    // 9. x1 = x + att @ Wo + bo
    {
        dim3 grid(DMODEL / 128, MTOK / 128);
        tf32_gemm<0><<<grid, 256, SMEM_BYTES>>>(att, nullptr, wo_t, bo, x, x1,
                                                MTOK, DMODEL, DMODEL);
    }
    // 10. h2 = rmsnorm(x1); gate = softmax(h2 @ Wg + bg)
    rms2_gate_kernel<<<MTOK, 256>>>(x1, gamma2, Wg, bg, h2, gate);
    // 11. out = x1 + MoE(h2)
    {
        dim3 grid(DMODEL / 128, MTOK / 128);
        tf32_gemm<1><<<grid, 256, SMEM_BYTES>>>(h2, gate, we_t, nullptr, x1, out,
                                                MTOK, DMODEL, NEXP * DMODEL);
    }
}